// round 1
// baseline (speedup 1.0000x reference)
#include <cuda_runtime.h>

#define NN 50000
#define EMAX 800000
#define EPS 1e-5f

// ---------------- scratch (static device memory; no allocs allowed) ----------------
__device__ float g_mean[NN * 256];
__device__ float g_hA[NN * 256];
__device__ float g_hB[NN * 256];
__device__ int   g_counts[NN];
__device__ int   g_offsets[NN + 1];
__device__ int   g_cursor[NN];
__device__ int   g_esrc[EMAX];

// ---------------- CSR build ----------------
__global__ void zero_counts_kernel() {
    int i = blockIdx.x * blockDim.x + threadIdx.x;
    if (i < NN) g_counts[i] = 0;
}

__global__ void hist_kernel(const int* __restrict__ dst, int E) {
    int e = blockIdx.x * blockDim.x + threadIdx.x;
    if (e < E) atomicAdd(&g_counts[dst[e]], 1);
}

// single-block exclusive scan over 50001 entries; also zeroes cursors
__global__ void scan_kernel() {
    __shared__ int s[1024];
    __shared__ int carry;
    int tid = threadIdx.x;
    if (tid == 0) carry = 0;
    __syncthreads();
    for (int base = 0; base < NN; base += 1024) {
        int i = base + tid;
        int v = (i < NN) ? g_counts[i] : 0;
        s[tid] = v;
        __syncthreads();
        #pragma unroll
        for (int off = 1; off < 1024; off <<= 1) {
            int t = (tid >= off) ? s[tid - off] : 0;
            __syncthreads();
            s[tid] += t;
            __syncthreads();
        }
        int incl = s[tid];
        if (i < NN) {
            g_offsets[i] = carry + incl - v;   // exclusive prefix
            g_cursor[i] = 0;
        }
        __syncthreads();
        if (tid == 1023) carry += incl;
        __syncthreads();
    }
    if (tid == 0) g_offsets[NN] = carry;
}

__global__ void scatter_kernel(const int* __restrict__ src,
                               const int* __restrict__ dst, int E) {
    int e = blockIdx.x * blockDim.x + threadIdx.x;
    if (e < E) {
        int d = dst[e];
        int p = atomicAdd(&g_cursor[d], 1);
        g_esrc[g_offsets[d] + p] = src[e];
    }
}

// ---------------- mean aggregation: one warp per node ----------------
// V = number of float4 per lane (D = V*128 features)
template <int V>
__global__ void agg_kernel(const float* __restrict__ h, float* __restrict__ mean) {
    int w = (blockIdx.x * blockDim.x + threadIdx.x) >> 5;
    if (w >= NN) return;
    int lane = threadIdx.x & 31;
    int beg = g_offsets[w];
    int end = g_offsets[w + 1];
    const int D = V * 128;

    float4 acc[V];
    #pragma unroll
    for (int v = 0; v < V; v++) acc[v] = make_float4(0.f, 0.f, 0.f, 0.f);

    for (int e = beg; e < end; e++) {
        long s = g_esrc[e];
        const float4* row = reinterpret_cast<const float4*>(h + s * (long)D);
        #pragma unroll
        for (int v = 0; v < V; v++) {
            float4 t = __ldg(&row[lane + 32 * v]);
            acc[v].x += t.x; acc[v].y += t.y; acc[v].z += t.z; acc[v].w += t.w;
        }
    }
    int deg = end - beg;
    float inv = 1.0f / (float)(deg > 1 ? deg : 1);
    float4* orow = reinterpret_cast<float4*>(mean + (long)w * D);
    #pragma unroll
    for (int v = 0; v < V; v++) {
        acc[v].x *= inv; acc[v].y *= inv; acc[v].z *= inv; acc[v].w *= inv;
        orow[lane + 32 * v] = acc[v];
    }
}

// ---------------- fused dual-GEMM + bias + BN (+ReLU) ----------------
// out[m,n] = BN( mean[m,:]@W1[:,n] + xin[m,:]@W2[:,n] + bias[n] )
// BM=64, BN=128, BK=16, TM=4, TN=8, 256 threads
template <int K, bool RELU>
__global__ __launch_bounds__(256) void sage_gemm_kernel(
    const float* __restrict__ A1, const float* __restrict__ A2,
    const float* __restrict__ W1, const float* __restrict__ W2,
    const float* __restrict__ bias,
    const float* __restrict__ gamma, const float* __restrict__ beta,
    const float* __restrict__ rmean, const float* __restrict__ rvar,
    float* __restrict__ out, int M)
{
    constexpr int BM = 64, BNc = 128, BK = 16, TM = 4, TN = 8;
    __shared__ float As[BK][BM];
    __shared__ float Bs[BK][BNc];

    int tid = threadIdx.x;
    int tx = tid & 15;          // 0..15  -> N
    int ty = tid >> 4;          // 0..15  -> M
    int rowBase = blockIdx.y * BM;
    int colBase = blockIdx.x * BNc;

    float acc[TM][TN];
    #pragma unroll
    for (int i = 0; i < TM; i++)
        #pragma unroll
        for (int j = 0; j < TN; j++) acc[i][j] = 0.f;

    #pragma unroll
    for (int mat = 0; mat < 2; mat++) {
        const float* A = mat ? A2 : A1;
        const float* W = mat ? W2 : W1;
        for (int k0 = 0; k0 < K; k0 += BK) {
            // load A tile (64x16) as one float4 per thread, store transposed
            {
                int am = tid >> 2;
                int ak4 = (tid & 3) * 4;
                int row = rowBase + am;
                float4 v = make_float4(0.f, 0.f, 0.f, 0.f);
                if (row < M)
                    v = *reinterpret_cast<const float4*>(&A[(long)row * K + k0 + ak4]);
                As[ak4 + 0][am] = v.x;
                As[ak4 + 1][am] = v.y;
                As[ak4 + 2][am] = v.z;
                As[ak4 + 3][am] = v.w;
            }
            // load B tile (16x128), 8 floats per thread, coalesced
            #pragma unroll
            for (int i = 0; i < 8; i++) {
                int idx = tid + i * 256;
                int bk = idx >> 7;
                int bn = idx & 127;
                Bs[bk][bn] = W[(long)(k0 + bk) * 256 + colBase + bn];
            }
            __syncthreads();

            #pragma unroll
            for (int k = 0; k < BK; k++) {
                float4 av  = *reinterpret_cast<const float4*>(&As[k][ty * TM]);
                float4 bv0 = *reinterpret_cast<const float4*>(&Bs[k][tx * TN]);
                float4 bv1 = *reinterpret_cast<const float4*>(&Bs[k][tx * TN + 4]);
                float a[TM] = {av.x, av.y, av.z, av.w};
                float b[TN] = {bv0.x, bv0.y, bv0.z, bv0.w, bv1.x, bv1.y, bv1.z, bv1.w};
                #pragma unroll
                for (int i = 0; i < TM; i++)
                    #pragma unroll
                    for (int j = 0; j < TN; j++)
                        acc[i][j] += a[i] * b[j];
            }
            __syncthreads();
        }
    }

    // epilogue: bias + BN (+ReLU)
    #pragma unroll
    for (int j = 0; j < TN; j++) {
        int col = colBase + tx * TN + j;
        float scale = gamma[col] * rsqrtf(rvar[col] + EPS);
        float shift = beta[col] - rmean[col] * scale;
        float bb = bias[col];
        #pragma unroll
        for (int i = 0; i < TM; i++) {
            int row = rowBase + ty * TM + i;
            if (row < M) {
                float v = (acc[i][j] + bb) * scale + shift;
                if (RELU) v = fmaxf(v, 0.f);
                out[(long)row * 256 + col] = v;
            }
        }
    }
}

// ---------------- launch ----------------
extern "C" void kernel_launch(void* const* d_in, const int* in_sizes, int n_in,
                              void* d_out, int out_size) {
    const float* x  = (const float*)d_in[0];
    const int*   ei = (const int*)d_in[1];
    int E = in_sizes[1] / 2;
    const int* src = ei;
    const int* dst = ei + E;

    const float* Wl0 = (const float*)d_in[2];
    const float* bl0 = (const float*)d_in[3];
    const float* Wr0 = (const float*)d_in[4];
    const float* g0  = (const float*)d_in[5];
    const float* b0  = (const float*)d_in[6];
    const float* rm0 = (const float*)d_in[7];
    const float* rv0 = (const float*)d_in[8];

    const float* Wl1 = (const float*)d_in[9];
    const float* bl1 = (const float*)d_in[10];
    const float* Wr1 = (const float*)d_in[11];
    const float* g1  = (const float*)d_in[12];
    const float* b1  = (const float*)d_in[13];
    const float* rm1 = (const float*)d_in[14];
    const float* rv1 = (const float*)d_in[15];

    const float* Wl2 = (const float*)d_in[16];
    const float* bl2 = (const float*)d_in[17];
    const float* Wr2 = (const float*)d_in[18];
    const float* g2  = (const float*)d_in[19];
    const float* b2  = (const float*)d_in[20];
    const float* rm2 = (const float*)d_in[21];
    const float* rv2 = (const float*)d_in[22];

    float *mean, *hA, *hB;
    cudaGetSymbolAddress((void**)&mean, g_mean);
    cudaGetSymbolAddress((void**)&hA, g_hA);
    cudaGetSymbolAddress((void**)&hB, g_hB);

    // CSR build
    zero_counts_kernel<<<(NN + 255) / 256, 256>>>();
    hist_kernel<<<(E + 255) / 256, 256>>>(dst, E);
    scan_kernel<<<1, 1024>>>();
    scatter_kernel<<<(E + 255) / 256, 256>>>(src, dst, E);

    dim3 gemm_grid(2, (NN + 63) / 64);
    int agg_blocks = (NN * 32 + 255) / 256;

    // layer 0: D_IN=128
    agg_kernel<1><<<agg_blocks, 256>>>(x, mean);
    sage_gemm_kernel<128, true><<<gemm_grid, 256>>>(
        mean, x, Wl0, Wr0, bl0, g0, b0, rm0, rv0, hA, NN);

    // layer 1: H=256
    agg_kernel<2><<<agg_blocks, 256>>>(hA, mean);
    sage_gemm_kernel<256, true><<<gemm_grid, 256>>>(
        mean, hA, Wl1, Wr1, bl1, g1, b1, rm1, rv1, hB, NN);

    // layer 2: H=256, no ReLU
    agg_kernel<2><<<agg_blocks, 256>>>(hB, mean);
    sage_gemm_kernel<256, false><<<gemm_grid, 256>>>(
        mean, hB, Wl2, Wr2, bl2, g2, b2, rm2, rv2, (float*)d_out, NN);
}

// round 3
// speedup vs baseline: 2.4237x; 2.4237x over previous
#include <cuda_runtime.h>
#include <cuda_bf16.h>
#include <cstdint>

#define NN 50000
#define EMAX 800000
#define EPS 1e-5f

// ======================= split bf16 pack/unpack =======================
__device__ __forceinline__ uint32_t pack_bf(float v) {
    __nv_bfloat16 h = __float2bfloat16(v);
    float hf = __bfloat162float(h);
    __nv_bfloat16 l = __float2bfloat16(v - hf);
    return ((uint32_t)__bfloat16_as_ushort(h) << 16) | (uint32_t)__bfloat16_as_ushort(l);
}
__device__ __forceinline__ float unpack_add(uint32_t u) {
    return __uint_as_float(u & 0xffff0000u) + __uint_as_float(u << 16);
}

// ======================= scratch =======================
__device__ uint32_t g_X[NN * 128];      // x packed split-bf16
__device__ uint32_t g_h1[NN * 256];     // activations (packed)
__device__ uint32_t g_h2[NN * 256];
__device__ uint32_t g_M[NN * 256];      // mean (packed)
// weights: bf16 hi/lo planes, transposed [mat][n][k]
__device__ __align__(16) __nv_bfloat16 g_Bh[2 * 256 * 128 + 2 * 2 * 256 * 256];
__device__ __align__(16) __nv_bfloat16 g_Bl[2 * 256 * 128 + 2 * 2 * 256 * 256];
__device__ int g_counts[NN];
__device__ int g_offsets[NN + 1];
__device__ int g_cursor[NN];
__device__ int g_esrc[EMAX];

// ======================= CSR build =======================
__global__ void zero_counts_kernel() {
    int i = blockIdx.x * blockDim.x + threadIdx.x;
    if (i < NN) g_counts[i] = 0;
}
__global__ void hist_kernel(const int* __restrict__ dst, int E) {
    int e = blockIdx.x * blockDim.x + threadIdx.x;
    if (e < E) atomicAdd(&g_counts[dst[e]], 1);
}
__global__ void scan_kernel() {
    __shared__ int s[1024];
    __shared__ int carry;
    int tid = threadIdx.x;
    if (tid == 0) carry = 0;
    __syncthreads();
    for (int base = 0; base < NN; base += 1024) {
        int i = base + tid;
        int v = (i < NN) ? g_counts[i] : 0;
        s[tid] = v;
        __syncthreads();
        #pragma unroll
        for (int off = 1; off < 1024; off <<= 1) {
            int t = (tid >= off) ? s[tid - off] : 0;
            __syncthreads();
            s[tid] += t;
            __syncthreads();
        }
        int incl = s[tid];
        if (i < NN) { g_offsets[i] = carry + incl - v; g_cursor[i] = 0; }
        __syncthreads();
        if (tid == 1023) carry += incl;
        __syncthreads();
    }
    if (tid == 0) g_offsets[NN] = carry;
}
__global__ void scatter_kernel(const int* __restrict__ src, const int* __restrict__ dst, int E) {
    int e = blockIdx.x * blockDim.x + threadIdx.x;
    if (e < E) {
        int d = dst[e];
        int p = atomicAdd(&g_cursor[d], 1);
        g_esrc[g_offsets[d] + p] = src[e];
    }
}

// ======================= conversion =======================
__global__ void conv_x_kernel(const float* __restrict__ x) {
    int i = blockIdx.x * blockDim.x + threadIdx.x;
    if (i < NN * 128) g_X[i] = pack_bf(x[i]);
}
// W[K,256] fp32 -> hi/lo planes at [mat][n][k]
__global__ void conv_w_kernel(const float* __restrict__ Wl, const float* __restrict__ Wr,
                              __nv_bfloat16* __restrict__ Bh, __nv_bfloat16* __restrict__ Bl,
                              int K) {
    int i = blockIdx.x * blockDim.x + threadIdx.x;
    int tot = 2 * 256 * K;
    if (i >= tot) return;
    int mat = i / (256 * K);
    int r = i - mat * 256 * K;
    int n = r / K;
    int k = r - n * K;
    const float* W = mat ? Wr : Wl;
    float f = W[k * 256 + n];
    __nv_bfloat16 h = __float2bfloat16(f);
    __nv_bfloat16 l = __float2bfloat16(f - __bfloat162float(h));
    Bh[i] = h;
    Bl[i] = l;
}

// ======================= mean aggregation (packed) =======================
template <int KP>
__global__ void agg_packed(const uint32_t* __restrict__ h, uint32_t* __restrict__ mean) {
    int w = (blockIdx.x * blockDim.x + threadIdx.x) >> 5;
    if (w >= NN) return;
    int lane = threadIdx.x & 31;
    int beg = g_offsets[w], end = g_offsets[w + 1];
    constexpr int IT = KP / 128;

    float acc[IT][4];
    #pragma unroll
    for (int it = 0; it < IT; it++)
        #pragma unroll
        for (int q = 0; q < 4; q++) acc[it][q] = 0.f;

    const uint4* base = reinterpret_cast<const uint4*>(h);
    for (int e = beg; e < end; e++) {
        int s = g_esrc[e];
        const uint4* p = base + (size_t)s * (KP / 4);
        #pragma unroll
        for (int it = 0; it < IT; it++) {
            uint4 t = __ldg(&p[lane + 32 * it]);
            acc[it][0] += unpack_add(t.x);
            acc[it][1] += unpack_add(t.y);
            acc[it][2] += unpack_add(t.z);
            acc[it][3] += unpack_add(t.w);
        }
    }
    int deg = end - beg;
    float inv = 1.0f / (float)(deg > 1 ? deg : 1);
    uint4* orow = reinterpret_cast<uint4*>(mean) + (size_t)w * (KP / 4);
    #pragma unroll
    for (int it = 0; it < IT; it++) {
        uint4 o;
        o.x = pack_bf(acc[it][0] * inv);
        o.y = pack_bf(acc[it][1] * inv);
        o.z = pack_bf(acc[it][2] * inv);
        o.w = pack_bf(acc[it][3] * inv);
        orow[lane + 32 * it] = o;
    }
}

// ======================= mma.sync helpers =======================
__device__ __forceinline__ void mma16816(float* c, const uint32_t* a, uint32_t b0, uint32_t b1) {
    asm("mma.sync.aligned.m16n8k16.row.col.f32.bf16.bf16.f32 "
        "{%0,%1,%2,%3}, {%4,%5,%6,%7}, {%8,%9}, {%0,%1,%2,%3};"
        : "+f"(c[0]), "+f"(c[1]), "+f"(c[2]), "+f"(c[3])
        : "r"(a[0]), "r"(a[1]), "r"(a[2]), "r"(a[3]), "r"(b0), "r"(b1));
}

// ======================= dual-GEMM (split bf16) + BN epilogue =======================
// CTA: 128(M) x 128(N), 8 warps as 4(M) x 2(N), warp tile 32x64.
// smem row stride 40 halves (80B): fragment loads conflict-free.
#define SST 40

template <int K, bool PACK_OUT, bool RELU>
__global__ __launch_bounds__(256) void gemm_mma(
    const uint32_t* __restrict__ A1, const uint32_t* __restrict__ A2,
    const __nv_bfloat16* __restrict__ Bh, const __nv_bfloat16* __restrict__ Bl,
    const float* __restrict__ blv, const float* __restrict__ gam,
    const float* __restrict__ bet, const float* __restrict__ rm,
    const float* __restrict__ rv,
    uint32_t* __restrict__ out, int M)
{
    __shared__ __align__(16) __nv_bfloat16 sAh[128 * SST];
    __shared__ __align__(16) __nv_bfloat16 sAl[128 * SST];
    __shared__ __align__(16) __nv_bfloat16 sBh[128 * SST];
    __shared__ __align__(16) __nv_bfloat16 sBl[128 * SST];

    int tid = threadIdx.x;
    int lane = tid & 31;
    int wid = tid >> 5;
    int g = lane >> 2;       // group row 0..7
    int tig = lane & 3;      // thread in group
    int wm = wid & 3;        // warp M index (0..3)
    int wn = wid >> 2;       // warp N index (0..1)
    int mBase = blockIdx.x * 128;
    int nBase = blockIdx.y * 128;

    float acc[2][8][4];
    #pragma unroll
    for (int mt = 0; mt < 2; mt++)
        #pragma unroll
        for (int nt = 0; nt < 8; nt++)
            #pragma unroll
            for (int q = 0; q < 4; q++) acc[mt][nt][q] = 0.f;

    #pragma unroll
    for (int mat = 0; mat < 2; mat++) {
        const uint32_t* A = mat ? A2 : A1;
        const __nv_bfloat16* BhM = Bh + (size_t)mat * 256 * K;
        const __nv_bfloat16* BlM = Bl + (size_t)mat * 256 * K;
        #pragma unroll
        for (int kc = 0; kc < K / 32; kc++) {
            __syncthreads();
            // ---- stage A: 128 rows x 32 packed u32 -> split hi/lo bf16 ----
            #pragma unroll
            for (int i = 0; i < 8; i++) {
                int lin = tid + i * 256;
                int row = lin >> 4;
                int c2 = lin & 15;
                int grow = mBase + row;
                uint2 v = make_uint2(0u, 0u);
                if (grow < M)
                    v = ((const uint2*)(A + (size_t)grow * K + kc * 32))[c2];
                uint32_t hu = (v.x >> 16) | (v.y & 0xffff0000u);
                uint32_t lu = (v.x & 0xffffu) | (v.y << 16);
                *(uint32_t*)&sAh[row * SST + c2 * 2] = hu;
                *(uint32_t*)&sAl[row * SST + c2 * 2] = lu;
            }
            // ---- stage B: 128 n-rows x 32 bf16 (hi & lo planes) ----
            #pragma unroll
            for (int i = 0; i < 8; i++) {
                int lin = tid + i * 256;
                int row = lin >> 4;
                int c = lin & 15;
                const uint32_t* ph = (const uint32_t*)(BhM + (size_t)(nBase + row) * K + kc * 32);
                const uint32_t* pl = (const uint32_t*)(BlM + (size_t)(nBase + row) * K + kc * 32);
                *(uint32_t*)&sBh[row * SST + c * 2] = ph[c];
                *(uint32_t*)&sBl[row * SST + c * 2] = pl[c];
            }
            __syncthreads();
            // ---- compute: 2 ksteps of 16 ----
            #pragma unroll
            for (int ks = 0; ks < 2; ks++) {
                int k0 = ks * 16;
                uint32_t ah[2][4], al[2][4];
                #pragma unroll
                for (int mt = 0; mt < 2; mt++) {
                    int r0 = (wm * 32 + mt * 16 + g) * SST + k0 + 2 * tig;
                    ah[mt][0] = *(const uint32_t*)&sAh[r0];
                    ah[mt][1] = *(const uint32_t*)&sAh[r0 + 8 * SST];
                    ah[mt][2] = *(const uint32_t*)&sAh[r0 + 8];
                    ah[mt][3] = *(const uint32_t*)&sAh[r0 + 8 * SST + 8];
                    al[mt][0] = *(const uint32_t*)&sAl[r0];
                    al[mt][1] = *(const uint32_t*)&sAl[r0 + 8 * SST];
                    al[mt][2] = *(const uint32_t*)&sAl[r0 + 8];
                    al[mt][3] = *(const uint32_t*)&sAl[r0 + 8 * SST + 8];
                }
                #pragma unroll
                for (int nt = 0; nt < 8; nt++) {
                    int b0 = (wn * 64 + nt * 8 + g) * SST + k0 + 2 * tig;
                    uint32_t bh0 = *(const uint32_t*)&sBh[b0];
                    uint32_t bh1 = *(const uint32_t*)&sBh[b0 + 8];
                    uint32_t bl0 = *(const uint32_t*)&sBl[b0];
                    uint32_t bl1 = *(const uint32_t*)&sBl[b0 + 8];
                    #pragma unroll
                    for (int mt = 0; mt < 2; mt++) {
                        mma16816(acc[mt][nt], ah[mt], bh0, bh1);
                        mma16816(acc[mt][nt], al[mt], bh0, bh1);
                        mma16816(acc[mt][nt], ah[mt], bl0, bl1);
                    }
                }
            }
        }
    }

    // ---- epilogue: bias+BN folded to per-col scale/shift ----
    #pragma unroll
    for (int nt = 0; nt < 8; nt++) {
        int c0 = nBase + wn * 64 + nt * 8 + 2 * tig;
        int c1 = c0 + 1;
        float sc0 = gam[c0] * rsqrtf(rv[c0] + EPS);
        float sh0 = (blv[c0] - rm[c0]) * sc0 + bet[c0];
        float sc1 = gam[c1] * rsqrtf(rv[c1] + EPS);
        float sh1 = (blv[c1] - rm[c1]) * sc1 + bet[c1];
        #pragma unroll
        for (int mt = 0; mt < 2; mt++) {
            int r0 = mBase + wm * 32 + mt * 16 + g;
            int r1 = r0 + 8;
            float v00 = acc[mt][nt][0] * sc0 + sh0;
            float v01 = acc[mt][nt][1] * sc1 + sh1;
            float v10 = acc[mt][nt][2] * sc0 + sh0;
            float v11 = acc[mt][nt][3] * sc1 + sh1;
            if (RELU) {
                v00 = fmaxf(v00, 0.f); v01 = fmaxf(v01, 0.f);
                v10 = fmaxf(v10, 0.f); v11 = fmaxf(v11, 0.f);
            }
            if (r0 < M) {
                uint2 w;
                w.x = PACK_OUT ? pack_bf(v00) : __float_as_uint(v00);
                w.y = PACK_OUT ? pack_bf(v01) : __float_as_uint(v01);
                *(uint2*)(out + (size_t)r0 * 256 + c0) = w;
            }
            if (r1 < M) {
                uint2 w;
                w.x = PACK_OUT ? pack_bf(v10) : __float_as_uint(v10);
                w.y = PACK_OUT ? pack_bf(v11) : __float_as_uint(v11);
                *(uint2*)(out + (size_t)r1 * 256 + c0) = w;
            }
        }
    }
}

// ======================= launch =======================
extern "C" void kernel_launch(void* const* d_in, const int* in_sizes, int n_in,
                              void* d_out, int out_size) {
    const float* x = (const float*)d_in[0];
    const int* ei = (const int*)d_in[1];
    int E = in_sizes[1] / 2;
    const int* src = ei;
    const int* dst = ei + E;

    const float* Wl0 = (const float*)d_in[2];
    const float* bl0 = (const float*)d_in[3];
    const float* Wr0 = (const float*)d_in[4];
    const float* g0 = (const float*)d_in[5];
    const float* b0 = (const float*)d_in[6];
    const float* rm0 = (const float*)d_in[7];
    const float* rv0 = (const float*)d_in[8];
    const float* Wl1 = (const float*)d_in[9];
    const float* bl1 = (const float*)d_in[10];
    const float* Wr1 = (const float*)d_in[11];
    const float* g1 = (const float*)d_in[12];
    const float* b1 = (const float*)d_in[13];
    const float* rm1 = (const float*)d_in[14];
    const float* rv1 = (const float*)d_in[15];
    const float* Wl2 = (const float*)d_in[16];
    const float* bl2 = (const float*)d_in[17];
    const float* Wr2 = (const float*)d_in[18];
    const float* g2 = (const float*)d_in[19];
    const float* b2 = (const float*)d_in[20];
    const float* rm2 = (const float*)d_in[21];
    const float* rv2 = (const float*)d_in[22];

    uint32_t *X, *h1, *h2, *Mn;
    __nv_bfloat16 *Bh, *Bl;
    cudaGetSymbolAddress((void**)&X, g_X);
    cudaGetSymbolAddress((void**)&h1, g_h1);
    cudaGetSymbolAddress((void**)&h2, g_h2);
    cudaGetSymbolAddress((void**)&Mn, g_M);
    cudaGetSymbolAddress((void**)&Bh, g_Bh);
    cudaGetSymbolAddress((void**)&Bl, g_Bl);
    __nv_bfloat16* Bh0 = Bh;
    __nv_bfloat16* Bh1 = Bh + 2 * 256 * 128;
    __nv_bfloat16* Bh2 = Bh1 + 2 * 256 * 256;
    __nv_bfloat16* Bl0 = Bl;
    __nv_bfloat16* Bl1 = Bl + 2 * 256 * 128;
    __nv_bfloat16* Bl2 = Bl1 + 2 * 256 * 256;

    // conversions
    conv_x_kernel<<<(NN * 128 + 255) / 256, 256>>>(x);
    conv_w_kernel<<<(2 * 256 * 128 + 255) / 256, 256>>>(Wl0, Wr0, Bh0, Bl0, 128);
    conv_w_kernel<<<(2 * 256 * 256 + 255) / 256, 256>>>(Wl1, Wr1, Bh1, Bl1, 256);
    conv_w_kernel<<<(2 * 256 * 256 + 255) / 256, 256>>>(Wl2, Wr2, Bh2, Bl2, 256);

    // CSR
    zero_counts_kernel<<<(NN + 255) / 256, 256>>>();
    hist_kernel<<<(E + 255) / 256, 256>>>(dst, E);
    scan_kernel<<<1, 1024>>>();
    scatter_kernel<<<(E + 255) / 256, 256>>>(src, dst, E);

    int agg_blocks = (NN * 32 + 255) / 256;
    dim3 gemm_grid((NN + 127) / 128, 2);

    // layer 0 (K=128)
    agg_packed<128><<<agg_blocks, 256>>>(X, Mn);
    gemm_mma<128, true, true><<<gemm_grid, 256>>>(
        Mn, X, Bh0, Bl0, bl0, g0, b0, rm0, rv0, h1, NN);

    // layer 1 (K=256)
    agg_packed<256><<<agg_blocks, 256>>>(h1, Mn);
    gemm_mma<256, true, true><<<gemm_grid, 256>>>(
        Mn, h1, Bh1, Bl1, bl1, g1, b1, rm1, rv1, h2, NN);

    // layer 2 (K=256, no ReLU, fp32 out)
    agg_packed<256><<<agg_blocks, 256>>>(h2, Mn);
    gemm_mma<256, false, false><<<gemm_grid, 256>>>(
        Mn, h2, Bh2, Bl2, bl2, g2, b2, rm2, rv2, (uint32_t*)d_out, NN);
}

// round 4
// speedup vs baseline: 2.4330x; 1.0038x over previous
#include <cuda_runtime.h>
#include <cuda_bf16.h>
#include <cstdint>

#define NN 50000
#define EMAX 800000
#define EPS 1e-5f

// ======================= split bf16 pack/unpack =======================
__device__ __forceinline__ uint32_t pack_bf(float v) {
    __nv_bfloat16 h = __float2bfloat16(v);
    float hf = __bfloat162float(h);
    __nv_bfloat16 l = __float2bfloat16(v - hf);
    return ((uint32_t)__bfloat16_as_ushort(h) << 16) | (uint32_t)__bfloat16_as_ushort(l);
}
__device__ __forceinline__ float unpack_add(uint32_t u) {
    return __uint_as_float(u & 0xffff0000u) + __uint_as_float(u << 16);
}

// ======================= scratch =======================
__device__ uint32_t g_X[NN * 128];      // x packed split-bf16
__device__ uint32_t g_h1[NN * 256];     // activations (packed)
__device__ uint32_t g_h2[NN * 256];
__device__ uint32_t g_M[NN * 256];      // mean (packed)
// weights: bf16 hi/lo planes, transposed [mat][n][k]
__device__ __align__(16) __nv_bfloat16 g_Bh[2 * 256 * 128 + 2 * 2 * 256 * 256];
__device__ __align__(16) __nv_bfloat16 g_Bl[2 * 256 * 128 + 2 * 2 * 256 * 256];
__device__ int g_counts[NN];
__device__ int g_offsets[NN + 1];
__device__ int g_cursor[NN];
__device__ int g_esrc[EMAX];

// ======================= CSR build =======================
__global__ void zero_counts_kernel() {
    int i = blockIdx.x * blockDim.x + threadIdx.x;
    if (i < NN) g_counts[i] = 0;
}
__global__ void hist_kernel(const int* __restrict__ dst, int E) {
    int e = blockIdx.x * blockDim.x + threadIdx.x;
    if (e < E) atomicAdd(&g_counts[dst[e]], 1);
}
__global__ void scan_kernel() {
    __shared__ int s[1024];
    __shared__ int carry;
    int tid = threadIdx.x;
    if (tid == 0) carry = 0;
    __syncthreads();
    for (int base = 0; base < NN; base += 1024) {
        int i = base + tid;
        int v = (i < NN) ? g_counts[i] : 0;
        s[tid] = v;
        __syncthreads();
        #pragma unroll
        for (int off = 1; off < 1024; off <<= 1) {
            int t = (tid >= off) ? s[tid - off] : 0;
            __syncthreads();
            s[tid] += t;
            __syncthreads();
        }
        int incl = s[tid];
        if (i < NN) { g_offsets[i] = carry + incl - v; g_cursor[i] = 0; }
        __syncthreads();
        if (tid == 1023) carry += incl;
        __syncthreads();
    }
    if (tid == 0) g_offsets[NN] = carry;
}
__global__ void scatter_kernel(const int* __restrict__ src, const int* __restrict__ dst, int E) {
    int e = blockIdx.x * blockDim.x + threadIdx.x;
    if (e < E) {
        int d = dst[e];
        int p = atomicAdd(&g_cursor[d], 1);
        g_esrc[g_offsets[d] + p] = src[e];
    }
}

// ======================= conversion =======================
__global__ void conv_x_kernel(const float* __restrict__ x) {
    int i = blockIdx.x * blockDim.x + threadIdx.x;
    if (i < NN * 128) g_X[i] = pack_bf(x[i]);
}
// W[K,256] fp32 -> hi/lo planes at [mat][n][k]
__global__ void conv_w_kernel(const float* __restrict__ Wl, const float* __restrict__ Wr,
                              __nv_bfloat16* __restrict__ Bh, __nv_bfloat16* __restrict__ Bl,
                              int K) {
    int i = blockIdx.x * blockDim.x + threadIdx.x;
    int tot = 2 * 256 * K;
    if (i >= tot) return;
    int mat = i / (256 * K);
    int r = i - mat * 256 * K;
    int n = r / K;
    int k = r - n * K;
    const float* W = mat ? Wr : Wl;
    float f = W[k * 256 + n];
    __nv_bfloat16 h = __float2bfloat16(f);
    __nv_bfloat16 l = __float2bfloat16(f - __bfloat162float(h));
    Bh[i] = h;
    Bl[i] = l;
}

// ======================= mean aggregation =======================
// One warp per 128-feature half of a node. NHALF = KP/128 (1 or 2).
// Edge loop unrolled x4 for MLP.
template <int NHALF>
__global__ __launch_bounds__(256) void agg_packed(const uint32_t* __restrict__ h,
                                                  uint32_t* __restrict__ mean) {
    int gw = (blockIdx.x * blockDim.x + threadIdx.x) >> 5;
    if (gw >= NN * NHALF) return;
    int node, half;
    if (NHALF == 2) { node = gw >> 1; half = gw & 1; }
    else            { node = gw;      half = 0; }
    int lane = threadIdx.x & 31;
    int beg = g_offsets[node], end = g_offsets[node + 1];

    // row stride in uint4 units; this warp's feature-half offset
    const int RS = NHALF * 32;
    const uint4* base = reinterpret_cast<const uint4*>(h) + half * 32 + lane;

    float a0 = 0.f, a1 = 0.f, a2 = 0.f, a3 = 0.f;
    int e = beg;
    for (; e + 4 <= end; e += 4) {
        int s0 = g_esrc[e + 0];
        int s1 = g_esrc[e + 1];
        int s2 = g_esrc[e + 2];
        int s3 = g_esrc[e + 3];
        uint4 t0 = __ldg(base + (size_t)s0 * RS);
        uint4 t1 = __ldg(base + (size_t)s1 * RS);
        uint4 t2 = __ldg(base + (size_t)s2 * RS);
        uint4 t3 = __ldg(base + (size_t)s3 * RS);
        a0 += unpack_add(t0.x) + unpack_add(t1.x) + unpack_add(t2.x) + unpack_add(t3.x);
        a1 += unpack_add(t0.y) + unpack_add(t1.y) + unpack_add(t2.y) + unpack_add(t3.y);
        a2 += unpack_add(t0.z) + unpack_add(t1.z) + unpack_add(t2.z) + unpack_add(t3.z);
        a3 += unpack_add(t0.w) + unpack_add(t1.w) + unpack_add(t2.w) + unpack_add(t3.w);
    }
    for (; e < end; e++) {
        int s = g_esrc[e];
        uint4 t = __ldg(base + (size_t)s * RS);
        a0 += unpack_add(t.x);
        a1 += unpack_add(t.y);
        a2 += unpack_add(t.z);
        a3 += unpack_add(t.w);
    }

    int deg = end - beg;
    float inv = 1.0f / (float)(deg > 1 ? deg : 1);
    uint4 o;
    o.x = pack_bf(a0 * inv);
    o.y = pack_bf(a1 * inv);
    o.z = pack_bf(a2 * inv);
    o.w = pack_bf(a3 * inv);
    reinterpret_cast<uint4*>(mean)[(size_t)node * RS + half * 32 + lane] = o;
}

// ======================= mma.sync helpers =======================
__device__ __forceinline__ void mma16816(float* c, const uint32_t* a, uint32_t b0, uint32_t b1) {
    asm("mma.sync.aligned.m16n8k16.row.col.f32.bf16.bf16.f32 "
        "{%0,%1,%2,%3}, {%4,%5,%6,%7}, {%8,%9}, {%0,%1,%2,%3};"
        : "+f"(c[0]), "+f"(c[1]), "+f"(c[2]), "+f"(c[3])
        : "r"(a[0]), "r"(a[1]), "r"(a[2]), "r"(a[3]), "r"(b0), "r"(b1));
}

// ======================= dual-GEMM (split bf16) + BN epilogue =======================
// CTA: 128(M) x 128(N), 8 warps as 4(M) x 2(N), warp tile 32x64.
#define SST 40

template <int K, bool PACK_OUT, bool RELU>
__global__ __launch_bounds__(256) void gemm_mma(
    const uint32_t* __restrict__ A1, const uint32_t* __restrict__ A2,
    const __nv_bfloat16* __restrict__ Bh, const __nv_bfloat16* __restrict__ Bl,
    const float* __restrict__ blv, const float* __restrict__ gam,
    const float* __restrict__ bet, const float* __restrict__ rm,
    const float* __restrict__ rv,
    uint32_t* __restrict__ out, int M)
{
    __shared__ __align__(16) __nv_bfloat16 sAh[128 * SST];
    __shared__ __align__(16) __nv_bfloat16 sAl[128 * SST];
    __shared__ __align__(16) __nv_bfloat16 sBh[128 * SST];
    __shared__ __align__(16) __nv_bfloat16 sBl[128 * SST];

    int tid = threadIdx.x;
    int lane = tid & 31;
    int wid = tid >> 5;
    int g = lane >> 2;
    int tig = lane & 3;
    int wm = wid & 3;
    int wn = wid >> 2;
    int mBase = blockIdx.x * 128;
    int nBase = blockIdx.y * 128;

    float acc[2][8][4];
    #pragma unroll
    for (int mt = 0; mt < 2; mt++)
        #pragma unroll
        for (int nt = 0; nt < 8; nt++)
            #pragma unroll
            for (int q = 0; q < 4; q++) acc[mt][nt][q] = 0.f;

    #pragma unroll
    for (int mat = 0; mat < 2; mat++) {
        const uint32_t* A = mat ? A2 : A1;
        const __nv_bfloat16* BhM = Bh + (size_t)mat * 256 * K;
        const __nv_bfloat16* BlM = Bl + (size_t)mat * 256 * K;
        #pragma unroll
        for (int kc = 0; kc < K / 32; kc++) {
            __syncthreads();
            #pragma unroll
            for (int i = 0; i < 8; i++) {
                int lin = tid + i * 256;
                int row = lin >> 4;
                int c2 = lin & 15;
                int grow = mBase + row;
                uint2 v = make_uint2(0u, 0u);
                if (grow < M)
                    v = ((const uint2*)(A + (size_t)grow * K + kc * 32))[c2];
                uint32_t hu = (v.x >> 16) | (v.y & 0xffff0000u);
                uint32_t lu = (v.x & 0xffffu) | (v.y << 16);
                *(uint32_t*)&sAh[row * SST + c2 * 2] = hu;
                *(uint32_t*)&sAl[row * SST + c2 * 2] = lu;
            }
            #pragma unroll
            for (int i = 0; i < 8; i++) {
                int lin = tid + i * 256;
                int row = lin >> 4;
                int c = lin & 15;
                const uint32_t* ph = (const uint32_t*)(BhM + (size_t)(nBase + row) * K + kc * 32);
                const uint32_t* pl = (const uint32_t*)(BlM + (size_t)(nBase + row) * K + kc * 32);
                *(uint32_t*)&sBh[row * SST + c * 2] = ph[c];
                *(uint32_t*)&sBl[row * SST + c * 2] = pl[c];
            }
            __syncthreads();
            #pragma unroll
            for (int ks = 0; ks < 2; ks++) {
                int k0 = ks * 16;
                uint32_t ah[2][4], al[2][4];
                #pragma unroll
                for (int mt = 0; mt < 2; mt++) {
                    int r0 = (wm * 32 + mt * 16 + g) * SST + k0 + 2 * tig;
                    ah[mt][0] = *(const uint32_t*)&sAh[r0];
                    ah[mt][1] = *(const uint32_t*)&sAh[r0 + 8 * SST];
                    ah[mt][2] = *(const uint32_t*)&sAh[r0 + 8];
                    ah[mt][3] = *(const uint32_t*)&sAh[r0 + 8 * SST + 8];
                    al[mt][0] = *(const uint32_t*)&sAl[r0];
                    al[mt][1] = *(const uint32_t*)&sAl[r0 + 8 * SST];
                    al[mt][2] = *(const uint32_t*)&sAl[r0 + 8];
                    al[mt][3] = *(const uint32_t*)&sAl[r0 + 8 * SST + 8];
                }
                #pragma unroll
                for (int nt = 0; nt < 8; nt++) {
                    int b0 = (wn * 64 + nt * 8 + g) * SST + k0 + 2 * tig;
                    uint32_t bh0 = *(const uint32_t*)&sBh[b0];
                    uint32_t bh1 = *(const uint32_t*)&sBh[b0 + 8];
                    uint32_t bl0 = *(const uint32_t*)&sBl[b0];
                    uint32_t bl1 = *(const uint32_t*)&sBl[b0 + 8];
                    #pragma unroll
                    for (int mt = 0; mt < 2; mt++) {
                        mma16816(acc[mt][nt], ah[mt], bh0, bh1);
                        mma16816(acc[mt][nt], al[mt], bh0, bh1);
                        mma16816(acc[mt][nt], ah[mt], bl0, bl1);
                    }
                }
            }
        }
    }

    #pragma unroll
    for (int nt = 0; nt < 8; nt++) {
        int c0 = nBase + wn * 64 + nt * 8 + 2 * tig;
        int c1 = c0 + 1;
        float sc0 = gam[c0] * rsqrtf(rv[c0] + EPS);
        float sh0 = (blv[c0] - rm[c0]) * sc0 + bet[c0];
        float sc1 = gam[c1] * rsqrtf(rv[c1] + EPS);
        float sh1 = (blv[c1] - rm[c1]) * sc1 + bet[c1];
        #pragma unroll
        for (int mt = 0; mt < 2; mt++) {
            int r0 = mBase + wm * 32 + mt * 16 + g;
            int r1 = r0 + 8;
            float v00 = acc[mt][nt][0] * sc0 + sh0;
            float v01 = acc[mt][nt][1] * sc1 + sh1;
            float v10 = acc[mt][nt][2] * sc0 + sh0;
            float v11 = acc[mt][nt][3] * sc1 + sh1;
            if (RELU) {
                v00 = fmaxf(v00, 0.f); v01 = fmaxf(v01, 0.f);
                v10 = fmaxf(v10, 0.f); v11 = fmaxf(v11, 0.f);
            }
            if (r0 < M) {
                uint2 w;
                w.x = PACK_OUT ? pack_bf(v00) : __float_as_uint(v00);
                w.y = PACK_OUT ? pack_bf(v01) : __float_as_uint(v01);
                *(uint2*)(out + (size_t)r0 * 256 + c0) = w;
            }
            if (r1 < M) {
                uint2 w;
                w.x = PACK_OUT ? pack_bf(v10) : __float_as_uint(v10);
                w.y = PACK_OUT ? pack_bf(v11) : __float_as_uint(v11);
                *(uint2*)(out + (size_t)r1 * 256 + c0) = w;
            }
        }
    }
}

// ======================= launch =======================
extern "C" void kernel_launch(void* const* d_in, const int* in_sizes, int n_in,
                              void* d_out, int out_size) {
    const float* x = (const float*)d_in[0];
    const int* ei = (const int*)d_in[1];
    int E = in_sizes[1] / 2;
    const int* src = ei;
    const int* dst = ei + E;

    const float* Wl0 = (const float*)d_in[2];
    const float* bl0 = (const float*)d_in[3];
    const float* Wr0 = (const float*)d_in[4];
    const float* g0 = (const float*)d_in[5];
    const float* b0 = (const float*)d_in[6];
    const float* rm0 = (const float*)d_in[7];
    const float* rv0 = (const float*)d_in[8];
    const float* Wl1 = (const float*)d_in[9];
    const float* bl1 = (const float*)d_in[10];
    const float* Wr1 = (const float*)d_in[11];
    const float* g1 = (const float*)d_in[12];
    const float* b1 = (const float*)d_in[13];
    const float* rm1 = (const float*)d_in[14];
    const float* rv1 = (const float*)d_in[15];
    const float* Wl2 = (const float*)d_in[16];
    const float* bl2 = (const float*)d_in[17];
    const float* Wr2 = (const float*)d_in[18];
    const float* g2 = (const float*)d_in[19];
    const float* b2 = (const float*)d_in[20];
    const float* rm2 = (const float*)d_in[21];
    const float* rv2 = (const float*)d_in[22];

    uint32_t *X, *h1, *h2, *Mn;
    __nv_bfloat16 *Bh, *Bl;
    cudaGetSymbolAddress((void**)&X, g_X);
    cudaGetSymbolAddress((void**)&h1, g_h1);
    cudaGetSymbolAddress((void**)&h2, g_h2);
    cudaGetSymbolAddress((void**)&Mn, g_M);
    cudaGetSymbolAddress((void**)&Bh, g_Bh);
    cudaGetSymbolAddress((void**)&Bl, g_Bl);
    __nv_bfloat16* Bh0 = Bh;
    __nv_bfloat16* Bh1 = Bh + 2 * 256 * 128;
    __nv_bfloat16* Bh2 = Bh1 + 2 * 256 * 256;
    __nv_bfloat16* Bl0 = Bl;
    __nv_bfloat16* Bl1 = Bl + 2 * 256 * 128;
    __nv_bfloat16* Bl2 = Bl1 + 2 * 256 * 256;

    // conversions
    conv_x_kernel<<<(NN * 128 + 255) / 256, 256>>>(x);
    conv_w_kernel<<<(2 * 256 * 128 + 255) / 256, 256>>>(Wl0, Wr0, Bh0, Bl0, 128);
    conv_w_kernel<<<(2 * 256 * 256 + 255) / 256, 256>>>(Wl1, Wr1, Bh1, Bl1, 256);
    conv_w_kernel<<<(2 * 256 * 256 + 255) / 256, 256>>>(Wl2, Wr2, Bh2, Bl2, 256);

    // CSR
    zero_counts_kernel<<<(NN + 255) / 256, 256>>>();
    hist_kernel<<<(E + 255) / 256, 256>>>(dst, E);
    scan_kernel<<<1, 1024>>>();
    scatter_kernel<<<(E + 255) / 256, 256>>>(src, dst, E);

    int agg_blocks1 = (NN * 32 + 255) / 256;        // NHALF=1
    int agg_blocks2 = (NN * 2 * 32 + 255) / 256;    // NHALF=2
    dim3 gemm_grid((NN + 127) / 128, 2);

    // layer 0 (K=128)
    agg_packed<1><<<agg_blocks1, 256>>>(X, Mn);
    gemm_mma<128, true, true><<<gemm_grid, 256>>>(
        Mn, X, Bh0, Bl0, bl0, g0, b0, rm0, rv0, h1, NN);

    // layer 1 (K=256)
    agg_packed<2><<<agg_blocks2, 256>>>(h1, Mn);
    gemm_mma<256, true, true><<<gemm_grid, 256>>>(
        Mn, h1, Bh1, Bl1, bl1, g1, b1, rm1, rv1, h2, NN);

    // layer 2 (K=256, no ReLU, fp32 out)
    agg_packed<2><<<agg_blocks2, 256>>>(h2, Mn);
    gemm_mma<256, false, false><<<gemm_grid, 256>>>(
        Mn, h2, Bh2, Bl2, bl2, g2, b2, rm2, rv2, (uint32_t*)d_out, NN);
}

// round 5
// speedup vs baseline: 2.5281x; 1.0391x over previous
#include <cuda_runtime.h>
#include <cuda_bf16.h>
#include <cstdint>

#define NN 50000
#define EMAX 800000
#define EPS 1e-5f

// ======================= split bf16 pack/unpack =======================
__device__ __forceinline__ uint32_t pack_bf(float v) {
    __nv_bfloat16 h = __float2bfloat16(v);
    float hf = __bfloat162float(h);
    __nv_bfloat16 l = __float2bfloat16(v - hf);
    return ((uint32_t)__bfloat16_as_ushort(h) << 16) | (uint32_t)__bfloat16_as_ushort(l);
}
__device__ __forceinline__ float unpack_add(uint32_t u) {
    return __uint_as_float(u & 0xffff0000u) + __uint_as_float(u << 16);
}

// ======================= scratch =======================
__device__ uint32_t g_X[NN * 128];
__device__ uint32_t g_h1[NN * 256];
__device__ uint32_t g_h2[NN * 256];
__device__ uint32_t g_M[NN * 256];
__device__ float    g_P[NN * 256];      // fp32 partial: x @ Wr
__device__ __align__(16) __nv_bfloat16 g_Bh[2 * 256 * 128 + 2 * 2 * 256 * 256];
__device__ __align__(16) __nv_bfloat16 g_Bl[2 * 256 * 128 + 2 * 2 * 256 * 256];
__device__ int g_counts[NN];
__device__ int g_offsets[NN + 1];
__device__ int g_cursor[NN];
__device__ int g_esrc[EMAX];

// ======================= CSR build =======================
__global__ void zero_counts_kernel() {
    int i = blockIdx.x * blockDim.x + threadIdx.x;
    if (i < NN) g_counts[i] = 0;
}
__global__ void hist_kernel(const int* __restrict__ dst, int E) {
    int e = blockIdx.x * blockDim.x + threadIdx.x;
    if (e < E) atomicAdd(&g_counts[dst[e]], 1);
}
__global__ void scan_kernel() {
    __shared__ int s[1024];
    __shared__ int carry;
    int tid = threadIdx.x;
    if (tid == 0) carry = 0;
    __syncthreads();
    for (int base = 0; base < NN; base += 1024) {
        int i = base + tid;
        int v = (i < NN) ? g_counts[i] : 0;
        s[tid] = v;
        __syncthreads();
        #pragma unroll
        for (int off = 1; off < 1024; off <<= 1) {
            int t = (tid >= off) ? s[tid - off] : 0;
            __syncthreads();
            s[tid] += t;
            __syncthreads();
        }
        int incl = s[tid];
        if (i < NN) { g_offsets[i] = carry + incl - v; g_cursor[i] = 0; }
        __syncthreads();
        if (tid == 1023) carry += incl;
        __syncthreads();
    }
    if (tid == 0) g_offsets[NN] = carry;
}
__global__ void scatter_kernel(const int* __restrict__ src, const int* __restrict__ dst, int E) {
    int e = blockIdx.x * blockDim.x + threadIdx.x;
    if (e < E) {
        int d = dst[e];
        int p = atomicAdd(&g_cursor[d], 1);
        g_esrc[g_offsets[d] + p] = src[e];
    }
}

// ======================= conversion =======================
__global__ void conv_x_kernel(const float* __restrict__ x) {
    int i = blockIdx.x * blockDim.x + threadIdx.x;
    if (i < NN * 128) g_X[i] = pack_bf(x[i]);
}
__global__ void conv_w_kernel(const float* __restrict__ Wl, const float* __restrict__ Wr,
                              __nv_bfloat16* __restrict__ Bh, __nv_bfloat16* __restrict__ Bl,
                              int K) {
    int i = blockIdx.x * blockDim.x + threadIdx.x;
    int tot = 2 * 256 * K;
    if (i >= tot) return;
    int mat = i / (256 * K);
    int r = i - mat * 256 * K;
    int n = r / K;
    int k = r - n * K;
    const float* W = mat ? Wr : Wl;
    float f = W[k * 256 + n];
    __nv_bfloat16 h = __float2bfloat16(f);
    __nv_bfloat16 l = __float2bfloat16(f - __bfloat162float(h));
    Bh[i] = h;
    Bl[i] = l;
}

// ======================= mean aggregation =======================
template <int NHALF>
__global__ __launch_bounds__(256) void agg_packed(const uint32_t* __restrict__ h,
                                                  uint32_t* __restrict__ mean) {
    int gw = (blockIdx.x * blockDim.x + threadIdx.x) >> 5;
    if (gw >= NN * NHALF) return;
    int node, half;
    if (NHALF == 2) { node = gw >> 1; half = gw & 1; }
    else            { node = gw;      half = 0; }
    int lane = threadIdx.x & 31;
    int beg = g_offsets[node], end = g_offsets[node + 1];

    const int RS = NHALF * 32;
    const uint4* base = reinterpret_cast<const uint4*>(h) + half * 32 + lane;

    float a0 = 0.f, a1 = 0.f, a2 = 0.f, a3 = 0.f;
    int e = beg;
    for (; e + 4 <= end; e += 4) {
        int s0 = g_esrc[e + 0];
        int s1 = g_esrc[e + 1];
        int s2 = g_esrc[e + 2];
        int s3 = g_esrc[e + 3];
        uint4 t0 = __ldg(base + (size_t)s0 * RS);
        uint4 t1 = __ldg(base + (size_t)s1 * RS);
        uint4 t2 = __ldg(base + (size_t)s2 * RS);
        uint4 t3 = __ldg(base + (size_t)s3 * RS);
        a0 += unpack_add(t0.x) + unpack_add(t1.x) + unpack_add(t2.x) + unpack_add(t3.x);
        a1 += unpack_add(t0.y) + unpack_add(t1.y) + unpack_add(t2.y) + unpack_add(t3.y);
        a2 += unpack_add(t0.z) + unpack_add(t1.z) + unpack_add(t2.z) + unpack_add(t3.z);
        a3 += unpack_add(t0.w) + unpack_add(t1.w) + unpack_add(t2.w) + unpack_add(t3.w);
    }
    for (; e < end; e++) {
        int s = g_esrc[e];
        uint4 t = __ldg(base + (size_t)s * RS);
        a0 += unpack_add(t.x);
        a1 += unpack_add(t.y);
        a2 += unpack_add(t.z);
        a3 += unpack_add(t.w);
    }

    int deg = end - beg;
    float inv = 1.0f / (float)(deg > 1 ? deg : 1);
    uint4 o;
    o.x = pack_bf(a0 * inv);
    o.y = pack_bf(a1 * inv);
    o.z = pack_bf(a2 * inv);
    o.w = pack_bf(a3 * inv);
    reinterpret_cast<uint4*>(mean)[(size_t)node * RS + half * 32 + lane] = o;
}

// ======================= mma.sync helper =======================
__device__ __forceinline__ void mma16816(float* c, const uint32_t* a, uint32_t b0, uint32_t b1) {
    asm("mma.sync.aligned.m16n8k16.row.col.f32.bf16.bf16.f32 "
        "{%0,%1,%2,%3}, {%4,%5,%6,%7}, {%8,%9}, {%0,%1,%2,%3};"
        : "+f"(c[0]), "+f"(c[1]), "+f"(c[2]), "+f"(c[3])
        : "r"(a[0]), "r"(a[1]), "r"(a[2]), "r"(a[3]), "r"(b0), "r"(b1));
}

// ======================= single-matrix GEMM (split bf16) =======================
// SELF:  out fp32 P = A@W (raw accumulators)
// !SELF: out = BN( A@W + P + bias ) [+ReLU], packed or fp32
#define SST 40

template <int K, bool SELF, bool PACK_OUT, bool RELU>
__global__ __launch_bounds__(256) void gemm_one(
    const uint32_t* __restrict__ A,
    const __nv_bfloat16* __restrict__ Bh, const __nv_bfloat16* __restrict__ Bl,
    const float* __restrict__ P,
    const float* __restrict__ blv, const float* __restrict__ gam,
    const float* __restrict__ bet, const float* __restrict__ rm,
    const float* __restrict__ rv,
    void* __restrict__ outv, int M)
{
    __shared__ __align__(16) __nv_bfloat16 sAh[128 * SST];
    __shared__ __align__(16) __nv_bfloat16 sAl[128 * SST];
    __shared__ __align__(16) __nv_bfloat16 sBh[128 * SST];
    __shared__ __align__(16) __nv_bfloat16 sBl[128 * SST];

    int tid = threadIdx.x;
    int lane = tid & 31;
    int wid = tid >> 5;
    int g = lane >> 2;
    int tig = lane & 3;
    int wm = wid & 3;
    int wn = wid >> 2;
    int mBase = blockIdx.x * 128;
    int nBase = blockIdx.y * 128;

    float acc[2][8][4];
    #pragma unroll
    for (int mt = 0; mt < 2; mt++)
        #pragma unroll
        for (int nt = 0; nt < 8; nt++)
            #pragma unroll
            for (int q = 0; q < 4; q++) acc[mt][nt][q] = 0.f;

    #pragma unroll
    for (int kc = 0; kc < K / 32; kc++) {
        __syncthreads();
        #pragma unroll
        for (int i = 0; i < 8; i++) {
            int lin = tid + i * 256;
            int row = lin >> 4;
            int c2 = lin & 15;
            int grow = mBase + row;
            uint2 v = make_uint2(0u, 0u);
            if (grow < M)
                v = ((const uint2*)(A + (size_t)grow * K + kc * 32))[c2];
            uint32_t hu = (v.x >> 16) | (v.y & 0xffff0000u);
            uint32_t lu = (v.x & 0xffffu) | (v.y << 16);
            *(uint32_t*)&sAh[row * SST + c2 * 2] = hu;
            *(uint32_t*)&sAl[row * SST + c2 * 2] = lu;
        }
        #pragma unroll
        for (int i = 0; i < 8; i++) {
            int lin = tid + i * 256;
            int row = lin >> 4;
            int c = lin & 15;
            const uint32_t* ph = (const uint32_t*)(Bh + (size_t)(nBase + row) * K + kc * 32);
            const uint32_t* pl = (const uint32_t*)(Bl + (size_t)(nBase + row) * K + kc * 32);
            *(uint32_t*)&sBh[row * SST + c * 2] = ph[c];
            *(uint32_t*)&sBl[row * SST + c * 2] = pl[c];
        }
        __syncthreads();
        #pragma unroll
        for (int ks = 0; ks < 2; ks++) {
            int k0 = ks * 16;
            uint32_t ah[2][4], al[2][4];
            #pragma unroll
            for (int mt = 0; mt < 2; mt++) {
                int r0 = (wm * 32 + mt * 16 + g) * SST + k0 + 2 * tig;
                ah[mt][0] = *(const uint32_t*)&sAh[r0];
                ah[mt][1] = *(const uint32_t*)&sAh[r0 + 8 * SST];
                ah[mt][2] = *(const uint32_t*)&sAh[r0 + 8];
                ah[mt][3] = *(const uint32_t*)&sAh[r0 + 8 * SST + 8];
                al[mt][0] = *(const uint32_t*)&sAl[r0];
                al[mt][1] = *(const uint32_t*)&sAl[r0 + 8 * SST];
                al[mt][2] = *(const uint32_t*)&sAl[r0 + 8];
                al[mt][3] = *(const uint32_t*)&sAl[r0 + 8 * SST + 8];
            }
            #pragma unroll
            for (int nt = 0; nt < 8; nt++) {
                int b0 = (wn * 64 + nt * 8 + g) * SST + k0 + 2 * tig;
                uint32_t bh0 = *(const uint32_t*)&sBh[b0];
                uint32_t bh1 = *(const uint32_t*)&sBh[b0 + 8];
                uint32_t bl0 = *(const uint32_t*)&sBl[b0];
                uint32_t bl1 = *(const uint32_t*)&sBl[b0 + 8];
                #pragma unroll
                for (int mt = 0; mt < 2; mt++) {
                    mma16816(acc[mt][nt], ah[mt], bh0, bh1);
                    mma16816(acc[mt][nt], al[mt], bh0, bh1);
                    mma16816(acc[mt][nt], ah[mt], bl0, bl1);
                }
            }
        }
    }

    if (SELF) {
        // write raw fp32 accumulators to P
        float* out = (float*)outv;
        #pragma unroll
        for (int nt = 0; nt < 8; nt++) {
            int c0 = nBase + wn * 64 + nt * 8 + 2 * tig;
            #pragma unroll
            for (int mt = 0; mt < 2; mt++) {
                int r0 = mBase + wm * 32 + mt * 16 + g;
                int r1 = r0 + 8;
                if (r0 < M)
                    *(float2*)(out + (size_t)r0 * 256 + c0) = make_float2(acc[mt][nt][0], acc[mt][nt][1]);
                if (r1 < M)
                    *(float2*)(out + (size_t)r1 * 256 + c0) = make_float2(acc[mt][nt][2], acc[mt][nt][3]);
            }
        }
    } else {
        uint32_t* out = (uint32_t*)outv;
        #pragma unroll
        for (int nt = 0; nt < 8; nt++) {
            int c0 = nBase + wn * 64 + nt * 8 + 2 * tig;
            int c1 = c0 + 1;
            float sc0 = gam[c0] * rsqrtf(rv[c0] + EPS);
            float sh0 = (blv[c0] - rm[c0]) * sc0 + bet[c0];
            float sc1 = gam[c1] * rsqrtf(rv[c1] + EPS);
            float sh1 = (blv[c1] - rm[c1]) * sc1 + bet[c1];
            #pragma unroll
            for (int mt = 0; mt < 2; mt++) {
                int r0 = mBase + wm * 32 + mt * 16 + g;
                int r1 = r0 + 8;
                if (r0 < M) {
                    float2 p = *(const float2*)(P + (size_t)r0 * 256 + c0);
                    float v00 = (acc[mt][nt][0] + p.x) * sc0 + sh0;
                    float v01 = (acc[mt][nt][1] + p.y) * sc1 + sh1;
                    if (RELU) { v00 = fmaxf(v00, 0.f); v01 = fmaxf(v01, 0.f); }
                    uint2 w;
                    w.x = PACK_OUT ? pack_bf(v00) : __float_as_uint(v00);
                    w.y = PACK_OUT ? pack_bf(v01) : __float_as_uint(v01);
                    *(uint2*)(out + (size_t)r0 * 256 + c0) = w;
                }
                if (r1 < M) {
                    float2 p = *(const float2*)(P + (size_t)r1 * 256 + c0);
                    float v10 = (acc[mt][nt][2] + p.x) * sc0 + sh0;
                    float v11 = (acc[mt][nt][3] + p.y) * sc1 + sh1;
                    if (RELU) { v10 = fmaxf(v10, 0.f); v11 = fmaxf(v11, 0.f); }
                    uint2 w;
                    w.x = PACK_OUT ? pack_bf(v10) : __float_as_uint(v10);
                    w.y = PACK_OUT ? pack_bf(v11) : __float_as_uint(v11);
                    *(uint2*)(out + (size_t)r1 * 256 + c0) = w;
                }
            }
        }
    }
}

// ======================= launch =======================
extern "C" void kernel_launch(void* const* d_in, const int* in_sizes, int n_in,
                              void* d_out, int out_size) {
    const float* x = (const float*)d_in[0];
    const int* ei = (const int*)d_in[1];
    int E = in_sizes[1] / 2;
    const int* src = ei;
    const int* dst = ei + E;

    const float* Wl0 = (const float*)d_in[2];
    const float* bl0 = (const float*)d_in[3];
    const float* Wr0 = (const float*)d_in[4];
    const float* g0 = (const float*)d_in[5];
    const float* b0 = (const float*)d_in[6];
    const float* rm0 = (const float*)d_in[7];
    const float* rv0 = (const float*)d_in[8];
    const float* Wl1 = (const float*)d_in[9];
    const float* bl1 = (const float*)d_in[10];
    const float* Wr1 = (const float*)d_in[11];
    const float* g1 = (const float*)d_in[12];
    const float* b1 = (const float*)d_in[13];
    const float* rm1 = (const float*)d_in[14];
    const float* rv1 = (const float*)d_in[15];
    const float* Wl2 = (const float*)d_in[16];
    const float* bl2 = (const float*)d_in[17];
    const float* Wr2 = (const float*)d_in[18];
    const float* g2 = (const float*)d_in[19];
    const float* b2 = (const float*)d_in[20];
    const float* rm2 = (const float*)d_in[21];
    const float* rv2 = (const float*)d_in[22];

    uint32_t *X, *h1, *h2, *Mn;
    float* P;
    __nv_bfloat16 *Bh, *Bl;
    cudaGetSymbolAddress((void**)&X, g_X);
    cudaGetSymbolAddress((void**)&h1, g_h1);
    cudaGetSymbolAddress((void**)&h2, g_h2);
    cudaGetSymbolAddress((void**)&Mn, g_M);
    cudaGetSymbolAddress((void**)&P, g_P);
    cudaGetSymbolAddress((void**)&Bh, g_Bh);
    cudaGetSymbolAddress((void**)&Bl, g_Bl);
    __nv_bfloat16* Bh0 = Bh;
    __nv_bfloat16* Bh1 = Bh + 2 * 256 * 128;
    __nv_bfloat16* Bh2 = Bh1 + 2 * 256 * 256;
    __nv_bfloat16* Bl0 = Bl;
    __nv_bfloat16* Bl1 = Bl + 2 * 256 * 128;
    __nv_bfloat16* Bl2 = Bl1 + 2 * 256 * 256;
    // per-matrix plane pointers: [mat=0]=Wl at offset 0, [mat=1]=Wr at offset 256*K
    __nv_bfloat16 *BhL0 = Bh0, *BhR0 = Bh0 + 256 * 128;
    __nv_bfloat16 *BlL0 = Bl0, *BlR0 = Bl0 + 256 * 128;
    __nv_bfloat16 *BhL1 = Bh1, *BhR1 = Bh1 + 256 * 256;
    __nv_bfloat16 *BlL1 = Bl1, *BlR1 = Bl1 + 256 * 256;
    __nv_bfloat16 *BhL2 = Bh2, *BhR2 = Bh2 + 256 * 256;
    __nv_bfloat16 *BlL2 = Bl2, *BlR2 = Bl2 + 256 * 256;

    cudaStream_t s1;
    cudaStreamCreateWithFlags(&s1, cudaStreamNonBlocking);
    cudaEvent_t evRoot, evX, evS0, evS1, evS2, evH1, evH2;
    cudaEventCreateWithFlags(&evRoot, cudaEventDisableTiming);
    cudaEventCreateWithFlags(&evX, cudaEventDisableTiming);
    cudaEventCreateWithFlags(&evS0, cudaEventDisableTiming);
    cudaEventCreateWithFlags(&evS1, cudaEventDisableTiming);
    cudaEventCreateWithFlags(&evS2, cudaEventDisableTiming);
    cudaEventCreateWithFlags(&evH1, cudaEventDisableTiming);
    cudaEventCreateWithFlags(&evH2, cudaEventDisableTiming);

    int agg_blocks1 = (NN * 32 + 255) / 256;
    int agg_blocks2 = (NN * 2 * 32 + 255) / 256;
    dim3 gg((NN + 127) / 128, 2);

    // fork side stream off the (captured) main stream
    cudaEventRecord(evRoot, 0);
    cudaStreamWaitEvent(s1, evRoot, 0);

    // ---- side stream: conversions + self-GEMMs ----
    conv_x_kernel<<<(NN * 128 + 255) / 256, 256, 0, s1>>>(x);
    cudaEventRecord(evX, s1);
    conv_w_kernel<<<(2 * 256 * 128 + 255) / 256, 256, 0, s1>>>(Wl0, Wr0, Bh0, Bl0, 128);
    conv_w_kernel<<<(2 * 256 * 256 + 255) / 256, 256, 0, s1>>>(Wl1, Wr1, Bh1, Bl1, 256);
    conv_w_kernel<<<(2 * 256 * 256 + 255) / 256, 256, 0, s1>>>(Wl2, Wr2, Bh2, Bl2, 256);
    gemm_one<128, true, false, false><<<gg, 256, 0, s1>>>(
        X, BhR0, BlR0, nullptr, nullptr, nullptr, nullptr, nullptr, nullptr, P, NN);
    cudaEventRecord(evS0, s1);

    // ---- main stream: CSR build ----
    zero_counts_kernel<<<(NN + 255) / 256, 256>>>();
    hist_kernel<<<(E + 255) / 256, 256>>>(dst, E);
    scan_kernel<<<1, 1024>>>();
    scatter_kernel<<<(E + 255) / 256, 256>>>(src, dst, E);

    // layer 0
    cudaStreamWaitEvent(0, evX, 0);
    agg_packed<1><<<agg_blocks1, 256>>>(X, Mn);
    cudaStreamWaitEvent(0, evS0, 0);
    gemm_one<128, false, true, true><<<gg, 256>>>(
        Mn, BhL0, BlL0, P, bl0, g0, b0, rm0, rv0, h1, NN);
    cudaEventRecord(evH1, 0);

    // side: self-GEMM layer 1 (h1 @ Wr1)
    cudaStreamWaitEvent(s1, evH1, 0);
    gemm_one<256, true, false, false><<<gg, 256, 0, s1>>>(
        h1, BhR1, BlR1, nullptr, nullptr, nullptr, nullptr, nullptr, nullptr, P, NN);
    cudaEventRecord(evS1, s1);

    // layer 1
    agg_packed<2><<<agg_blocks2, 256>>>(h1, Mn);
    cudaStreamWaitEvent(0, evS1, 0);
    gemm_one<256, false, true, true><<<gg, 256>>>(
        Mn, BhL1, BlL1, P, bl1, g1, b1, rm1, rv1, h2, NN);
    cudaEventRecord(evH2, 0);

    // side: self-GEMM layer 2 (h2 @ Wr2)
    cudaStreamWaitEvent(s1, evH2, 0);
    gemm_one<256, true, false, false><<<gg, 256, 0, s1>>>(
        h2, BhR2, BlR2, nullptr, nullptr, nullptr, nullptr, nullptr, nullptr, P, NN);
    cudaEventRecord(evS2, s1);

    // layer 2 (fp32 out, no ReLU)
    agg_packed<2><<<agg_blocks2, 256>>>(h2, Mn);
    cudaStreamWaitEvent(0, evS2, 0);
    gemm_one<256, false, false, false><<<gg, 256>>>(
        Mn, BhL2, BlL2, P, bl2, g2, b2, rm2, rv2, d_out, NN);

    cudaEventDestroy(evRoot);
    cudaEventDestroy(evX);
    cudaEventDestroy(evS0);
    cudaEventDestroy(evS1);
    cudaEventDestroy(evS2);
    cudaEventDestroy(evH1);
    cudaEventDestroy(evH2);
    cudaStreamDestroy(s1);
}

// round 7
// speedup vs baseline: 2.6845x; 1.0619x over previous
#include <cuda_runtime.h>
#include <cuda_bf16.h>
#include <cstdint>

#define NN 50000
#define EMAX 800000
#define EPS 1e-5f

// ======================= split bf16 pack/unpack =======================
__device__ __forceinline__ uint32_t pack_bf(float v) {
    __nv_bfloat16 h = __float2bfloat16(v);
    float hf = __bfloat162float(h);
    __nv_bfloat16 l = __float2bfloat16(v - hf);
    return ((uint32_t)__bfloat16_as_ushort(h) << 16) | (uint32_t)__bfloat16_as_ushort(l);
}
__device__ __forceinline__ float unpack_add(uint32_t u) {
    return __uint_as_float(u & 0xffff0000u) + __uint_as_float(u << 16);
}

__device__ __forceinline__ void cpasync16(uint32_t dst, const void* src) {
    asm volatile("cp.async.cg.shared.global [%0], [%1], 16;" :: "r"(dst), "l"(src));
}
__device__ __forceinline__ void cpcommit() { asm volatile("cp.async.commit_group;" ::: "memory"); }
__device__ __forceinline__ void cpwait0()  { asm volatile("cp.async.wait_group 0;" ::: "memory"); }

// ======================= scratch =======================
__device__ uint32_t g_X[NN * 128];
__device__ uint32_t g_h1[NN * 256];
__device__ uint32_t g_h2[NN * 256];
__device__ uint32_t g_M[NN * 256];
__device__ float    g_P[NN * 256];
__device__ __align__(16) __nv_bfloat16 g_Bh[2 * 256 * 128 + 2 * 2 * 256 * 256];
__device__ __align__(16) __nv_bfloat16 g_Bl[2 * 256 * 128 + 2 * 2 * 256 * 256];
__device__ int g_counts[NN];
__device__ int g_offsets[NN + 1];
__device__ int g_cursor[NN];
__device__ int g_esrc[EMAX];

// ======================= CSR build =======================
__global__ void zero_counts_kernel() {
    int i = blockIdx.x * blockDim.x + threadIdx.x;
    if (i < NN) g_counts[i] = 0;
}
__global__ void hist_kernel(const int* __restrict__ dst, int E) {
    int e = blockIdx.x * blockDim.x + threadIdx.x;
    if (e < E) atomicAdd(&g_counts[dst[e]], 1);
}
__global__ void scan_kernel() {
    __shared__ int s[1024];
    __shared__ int carry;
    int tid = threadIdx.x;
    if (tid == 0) carry = 0;
    __syncthreads();
    for (int base = 0; base < NN; base += 1024) {
        int i = base + tid;
        int v = (i < NN) ? g_counts[i] : 0;
        s[tid] = v;
        __syncthreads();
        #pragma unroll
        for (int off = 1; off < 1024; off <<= 1) {
            int t = (tid >= off) ? s[tid - off] : 0;
            __syncthreads();
            s[tid] += t;
            __syncthreads();
        }
        int incl = s[tid];
        if (i < NN) { g_offsets[i] = carry + incl - v; g_cursor[i] = 0; }
        __syncthreads();
        if (tid == 1023) carry += incl;
        __syncthreads();
    }
    if (tid == 0) g_offsets[NN] = carry;
}
__global__ void scatter_kernel(const int* __restrict__ src, const int* __restrict__ dst, int E) {
    int e = blockIdx.x * blockDim.x + threadIdx.x;
    if (e < E) {
        int d = dst[e];
        int p = atomicAdd(&g_cursor[d], 1);
        g_esrc[g_offsets[d] + p] = src[e];
    }
}

// ======================= conversion =======================
__global__ void conv_x_kernel(const float* __restrict__ x) {
    int i = blockIdx.x * blockDim.x + threadIdx.x;
    if (i < NN * 128) g_X[i] = pack_bf(x[i]);
}
__global__ void conv_w_kernel(const float* __restrict__ Wl, const float* __restrict__ Wr,
                              __nv_bfloat16* __restrict__ Bh, __nv_bfloat16* __restrict__ Bl,
                              int K) {
    int i = blockIdx.x * blockDim.x + threadIdx.x;
    int tot = 2 * 256 * K;
    if (i >= tot) return;
    int mat = i / (256 * K);
    int r = i - mat * 256 * K;
    int n = r / K;
    int k = r - n * K;
    const float* W = mat ? Wr : Wl;
    float f = W[k * 256 + n];
    __nv_bfloat16 h = __float2bfloat16(f);
    __nv_bfloat16 l = __float2bfloat16(f - __bfloat162float(h));
    Bh[i] = h;
    Bl[i] = l;
}

// ======================= mean aggregation =======================
template <int NHALF>
__global__ __launch_bounds__(256) void agg_packed(const uint32_t* __restrict__ h,
                                                  uint32_t* __restrict__ mean) {
    int gw = (blockIdx.x * blockDim.x + threadIdx.x) >> 5;
    if (gw >= NN * NHALF) return;
    int node, half;
    if (NHALF == 2) { node = gw >> 1; half = gw & 1; }
    else            { node = gw;      half = 0; }
    int lane = threadIdx.x & 31;
    int beg = g_offsets[node], end = g_offsets[node + 1];

    const int RS = NHALF * 32;
    const uint4* base = reinterpret_cast<const uint4*>(h) + half * 32 + lane;

    float a0 = 0.f, a1 = 0.f, a2 = 0.f, a3 = 0.f;
    int e = beg;
    for (; e + 4 <= end; e += 4) {
        int s0 = g_esrc[e + 0];
        int s1 = g_esrc[e + 1];
        int s2 = g_esrc[e + 2];
        int s3 = g_esrc[e + 3];
        uint4 t0 = __ldg(base + (size_t)s0 * RS);
        uint4 t1 = __ldg(base + (size_t)s1 * RS);
        uint4 t2 = __ldg(base + (size_t)s2 * RS);
        uint4 t3 = __ldg(base + (size_t)s3 * RS);
        a0 += unpack_add(t0.x) + unpack_add(t1.x) + unpack_add(t2.x) + unpack_add(t3.x);
        a1 += unpack_add(t0.y) + unpack_add(t1.y) + unpack_add(t2.y) + unpack_add(t3.y);
        a2 += unpack_add(t0.z) + unpack_add(t1.z) + unpack_add(t2.z) + unpack_add(t3.z);
        a3 += unpack_add(t0.w) + unpack_add(t1.w) + unpack_add(t2.w) + unpack_add(t3.w);
    }
    for (; e < end; e++) {
        int s = g_esrc[e];
        uint4 t = __ldg(base + (size_t)s * RS);
        a0 += unpack_add(t.x);
        a1 += unpack_add(t.y);
        a2 += unpack_add(t.z);
        a3 += unpack_add(t.w);
    }

    int deg = end - beg;
    float inv = 1.0f / (float)(deg > 1 ? deg : 1);
    uint4 o;
    o.x = pack_bf(a0 * inv);
    o.y = pack_bf(a1 * inv);
    o.z = pack_bf(a2 * inv);
    o.w = pack_bf(a3 * inv);
    reinterpret_cast<uint4*>(mean)[(size_t)node * RS + half * 32 + lane] = o;
}

// ======================= mma.sync helper =======================
__device__ __forceinline__ void mma16816(float* c, const uint32_t* a, uint32_t b0, uint32_t b1) {
    asm("mma.sync.aligned.m16n8k16.row.col.f32.bf16.bf16.f32 "
        "{%0,%1,%2,%3}, {%4,%5,%6,%7}, {%8,%9}, {%0,%1,%2,%3};"
        : "+f"(c[0]), "+f"(c[1]), "+f"(c[2]), "+f"(c[3])
        : "r"(a[0]), "r"(a[1]), "r"(a[2]), "r"(a[3]), "r"(b0), "r"(b1));
}

// ======================= double-buffered single-matrix GEMM =======================
#define SST 40
#define PLANE_B (128 * SST * 2)        // 10240 bytes per plane
#define BUF_B   (4 * PLANE_B)          // 40960 bytes per buffer
#define GSMEM   (2 * BUF_B)            // 81920 bytes

template <int K, bool SELF, bool PACK_OUT, bool RELU>
__global__ __launch_bounds__(256, 2) void gemm_one(
    const uint32_t* __restrict__ A,
    const __nv_bfloat16* __restrict__ Bh, const __nv_bfloat16* __restrict__ Bl,
    const float* __restrict__ P,
    const float* __restrict__ blv, const float* __restrict__ gam,
    const float* __restrict__ bet, const float* __restrict__ rm,
    const float* __restrict__ rv,
    void* __restrict__ outv, int M)
{
    extern __shared__ __align__(16) char dsm[];
    constexpr int NC = K / 32;

    int tid = threadIdx.x;
    int lane = tid & 31;
    int wid = tid >> 5;
    int g = lane >> 2;
    int tig = lane & 3;
    int wm = wid & 3;
    int wn = wid >> 2;
    int mBase = blockIdx.x * 128;
    int nBase = blockIdx.y * 128;

    float acc[2][8][4];
    #pragma unroll
    for (int mt = 0; mt < 2; mt++)
        #pragma unroll
        for (int nt = 0; nt < 8; nt++)
            #pragma unroll
            for (int q = 0; q < 4; q++) acc[mt][nt][q] = 0.f;

    // ---- staging helpers ----
    // B planes via cp.async: 128 rows x 32 halves (64B = 4x16B per row), 512 xfers/plane
    auto stageB = [&](int kc, int buf) {
        char* base = dsm + buf * BUF_B;
        uint32_t dBh = (uint32_t)__cvta_generic_to_shared(base + 2 * PLANE_B);
        uint32_t dBl = (uint32_t)__cvta_generic_to_shared(base + 3 * PLANE_B);
        #pragma unroll
        for (int i = 0; i < 2; i++) {
            int lin = tid + i * 256;
            int row = lin >> 2;      // 0..127
            int c8 = lin & 3;        // 16B chunk within row (0..3)
            uint32_t doff = (uint32_t)(row * (SST * 2) + c8 * 16);
            const __nv_bfloat16* sh = Bh + (size_t)(nBase + row) * K + kc * 32 + c8 * 8;
            const __nv_bfloat16* sl = Bl + (size_t)(nBase + row) * K + kc * 32 + c8 * 8;
            cpasync16(dBh + doff, sh);
            cpasync16(dBl + doff, sl);
        }
        cpcommit();
    };
    auto loadA = [&](int kc, uint2* pa) {
        #pragma unroll
        for (int i = 0; i < 8; i++) {
            int lin = tid + i * 256;
            int row = lin >> 4;
            int c2 = lin & 15;
            int grow = mBase + row;
            pa[i] = (grow < M) ? ((const uint2*)(A + (size_t)grow * K + kc * 32))[c2]
                               : make_uint2(0u, 0u);
        }
    };
    auto storeA = [&](int buf, const uint2* pa) {
        char* base = dsm + buf * BUF_B;
        __nv_bfloat16* sAh = (__nv_bfloat16*)(base);
        __nv_bfloat16* sAl = (__nv_bfloat16*)(base + PLANE_B);
        #pragma unroll
        for (int i = 0; i < 8; i++) {
            int lin = tid + i * 256;
            int row = lin >> 4;
            int c2 = lin & 15;
            uint32_t hu = (pa[i].x >> 16) | (pa[i].y & 0xffff0000u);
            uint32_t lu = (pa[i].x & 0xffffu) | (pa[i].y << 16);
            *(uint32_t*)&sAh[row * SST + c2 * 2] = hu;
            *(uint32_t*)&sAl[row * SST + c2 * 2] = lu;
        }
    };

    // ---- prologue: stage chunk 0 into buffer 0 ----
    uint2 pa[8];
    stageB(0, 0);
    loadA(0, pa);
    storeA(0, pa);
    cpwait0();
    __syncthreads();

    for (int kc = 0; kc < NC; kc++) {
        int cur = kc & 1;
        int nxt = cur ^ 1;
        bool more = (kc + 1 < NC);
        if (more) {
            stageB(kc + 1, nxt);
            loadA(kc + 1, pa);
        }
        // ---- compute on buffer cur ----
        {
            char* base = dsm + cur * BUF_B;
            const __nv_bfloat16* sAh = (const __nv_bfloat16*)(base);
            const __nv_bfloat16* sAl = (const __nv_bfloat16*)(base + PLANE_B);
            const __nv_bfloat16* sBh = (const __nv_bfloat16*)(base + 2 * PLANE_B);
            const __nv_bfloat16* sBl = (const __nv_bfloat16*)(base + 3 * PLANE_B);
            #pragma unroll
            for (int ks = 0; ks < 2; ks++) {
                int k0 = ks * 16;
                uint32_t ah[2][4], al[2][4];
                #pragma unroll
                for (int mt = 0; mt < 2; mt++) {
                    int r0 = (wm * 32 + mt * 16 + g) * SST + k0 + 2 * tig;
                    ah[mt][0] = *(const uint32_t*)&sAh[r0];
                    ah[mt][1] = *(const uint32_t*)&sAh[r0 + 8 * SST];
                    ah[mt][2] = *(const uint32_t*)&sAh[r0 + 8];
                    ah[mt][3] = *(const uint32_t*)&sAh[r0 + 8 * SST + 8];
                    al[mt][0] = *(const uint32_t*)&sAl[r0];
                    al[mt][1] = *(const uint32_t*)&sAl[r0 + 8 * SST];
                    al[mt][2] = *(const uint32_t*)&sAl[r0 + 8];
                    al[mt][3] = *(const uint32_t*)&sAl[r0 + 8 * SST + 8];
                }
                #pragma unroll
                for (int nt = 0; nt < 8; nt++) {
                    int b0 = (wn * 64 + nt * 8 + g) * SST + k0 + 2 * tig;
                    uint32_t bh0 = *(const uint32_t*)&sBh[b0];
                    uint32_t bh1 = *(const uint32_t*)&sBh[b0 + 8];
                    uint32_t bl0 = *(const uint32_t*)&sBl[b0];
                    uint32_t bl1 = *(const uint32_t*)&sBl[b0 + 8];
                    #pragma unroll
                    for (int mt = 0; mt < 2; mt++) {
                        mma16816(acc[mt][nt], ah[mt], bh0, bh1);
                        mma16816(acc[mt][nt], al[mt], bh0, bh1);
                        mma16816(acc[mt][nt], ah[mt], bl0, bl1);
                    }
                }
            }
        }
        if (more) {
            storeA(nxt, pa);
            cpwait0();
        }
        __syncthreads();
    }

    // ---- epilogue ----
    if (SELF) {
        float* out = (float*)outv;
        #pragma unroll
        for (int nt = 0; nt < 8; nt++) {
            int c0 = nBase + wn * 64 + nt * 8 + 2 * tig;
            #pragma unroll
            for (int mt = 0; mt < 2; mt++) {
                int r0 = mBase + wm * 32 + mt * 16 + g;
                int r1 = r0 + 8;
                if (r0 < M)
                    *(float2*)(out + (size_t)r0 * 256 + c0) = make_float2(acc[mt][nt][0], acc[mt][nt][1]);
                if (r1 < M)
                    *(float2*)(out + (size_t)r1 * 256 + c0) = make_float2(acc[mt][nt][2], acc[mt][nt][3]);
            }
        }
    } else {
        uint32_t* out = (uint32_t*)outv;
        #pragma unroll
        for (int nt = 0; nt < 8; nt++) {
            int c0 = nBase + wn * 64 + nt * 8 + 2 * tig;
            int c1 = c0 + 1;
            float sc0 = gam[c0] * rsqrtf(rv[c0] + EPS);
            float sh0 = (blv[c0] - rm[c0]) * sc0 + bet[c0];
            float sc1 = gam[c1] * rsqrtf(rv[c1] + EPS);
            float sh1 = (blv[c1] - rm[c1]) * sc1 + bet[c1];
            #pragma unroll
            for (int mt = 0; mt < 2; mt++) {
                int r0 = mBase + wm * 32 + mt * 16 + g;
                int r1 = r0 + 8;
                if (r0 < M) {
                    float2 p = *(const float2*)(P + (size_t)r0 * 256 + c0);
                    float v00 = (acc[mt][nt][0] + p.x) * sc0 + sh0;
                    float v01 = (acc[mt][nt][1] + p.y) * sc1 + sh1;
                    if (RELU) { v00 = fmaxf(v00, 0.f); v01 = fmaxf(v01, 0.f); }
                    uint2 w;
                    w.x = PACK_OUT ? pack_bf(v00) : __float_as_uint(v00);
                    w.y = PACK_OUT ? pack_bf(v01) : __float_as_uint(v01);
                    *(uint2*)(out + (size_t)r0 * 256 + c0) = w;
                }
                if (r1 < M) {
                    float2 p = *(const float2*)(P + (size_t)r1 * 256 + c0);
                    float v10 = (acc[mt][nt][2] + p.x) * sc0 + sh0;
                    float v11 = (acc[mt][nt][3] + p.y) * sc1 + sh1;
                    if (RELU) { v10 = fmaxf(v10, 0.f); v11 = fmaxf(v11, 0.f); }
                    uint2 w;
                    w.x = PACK_OUT ? pack_bf(v10) : __float_as_uint(v10);
                    w.y = PACK_OUT ? pack_bf(v11) : __float_as_uint(v11);
                    *(uint2*)(out + (size_t)r1 * 256 + c0) = w;
                }
            }
        }
    }
}

// ======================= launch =======================
extern "C" void kernel_launch(void* const* d_in, const int* in_sizes, int n_in,
                              void* d_out, int out_size) {
    const float* x = (const float*)d_in[0];
    const int* ei = (const int*)d_in[1];
    int E = in_sizes[1] / 2;
    const int* src = ei;
    const int* dst = ei + E;

    const float* Wl0 = (const float*)d_in[2];
    const float* bl0 = (const float*)d_in[3];
    const float* Wr0 = (const float*)d_in[4];
    const float* g0 = (const float*)d_in[5];
    const float* b0 = (const float*)d_in[6];
    const float* rm0 = (const float*)d_in[7];
    const float* rv0 = (const float*)d_in[8];
    const float* Wl1 = (const float*)d_in[9];
    const float* bl1 = (const float*)d_in[10];
    const float* Wr1 = (const float*)d_in[11];
    const float* g1 = (const float*)d_in[12];
    const float* b1 = (const float*)d_in[13];
    const float* rm1 = (const float*)d_in[14];
    const float* rv1 = (const float*)d_in[15];
    const float* Wl2 = (const float*)d_in[16];
    const float* bl2 = (const float*)d_in[17];
    const float* Wr2 = (const float*)d_in[18];
    const float* g2 = (const float*)d_in[19];
    const float* b2 = (const float*)d_in[20];
    const float* rm2 = (const float*)d_in[21];
    const float* rv2 = (const float*)d_in[22];

    uint32_t *X, *h1, *h2, *Mn;
    float* P;
    __nv_bfloat16 *Bh, *Bl;
    cudaGetSymbolAddress((void**)&X, g_X);
    cudaGetSymbolAddress((void**)&h1, g_h1);
    cudaGetSymbolAddress((void**)&h2, g_h2);
    cudaGetSymbolAddress((void**)&Mn, g_M);
    cudaGetSymbolAddress((void**)&P, g_P);
    cudaGetSymbolAddress((void**)&Bh, g_Bh);
    cudaGetSymbolAddress((void**)&Bl, g_Bl);
    __nv_bfloat16* Bh0 = Bh;
    __nv_bfloat16* Bh1 = Bh + 2 * 256 * 128;
    __nv_bfloat16* Bh2 = Bh1 + 2 * 256 * 256;
    __nv_bfloat16* Bl0 = Bl;
    __nv_bfloat16* Bl1 = Bl + 2 * 256 * 128;
    __nv_bfloat16* Bl2 = Bl1 + 2 * 256 * 256;
    __nv_bfloat16 *BhL0 = Bh0, *BhR0 = Bh0 + 256 * 128;
    __nv_bfloat16 *BlL0 = Bl0, *BlR0 = Bl0 + 256 * 128;
    __nv_bfloat16 *BhL1 = Bh1, *BhR1 = Bh1 + 256 * 256;
    __nv_bfloat16 *BlL1 = Bl1, *BlR1 = Bl1 + 256 * 256;
    __nv_bfloat16 *BhL2 = Bh2, *BhR2 = Bh2 + 256 * 256;
    __nv_bfloat16 *BlL2 = Bl2, *BlR2 = Bl2 + 256 * 256;

    cudaFuncSetAttribute(gemm_one<128, true, false, false>, cudaFuncAttributeMaxDynamicSharedMemorySize, GSMEM);
    cudaFuncSetAttribute(gemm_one<256, true, false, false>, cudaFuncAttributeMaxDynamicSharedMemorySize, GSMEM);
    cudaFuncSetAttribute(gemm_one<128, false, true, true>, cudaFuncAttributeMaxDynamicSharedMemorySize, GSMEM);
    cudaFuncSetAttribute(gemm_one<256, false, true, true>, cudaFuncAttributeMaxDynamicSharedMemorySize, GSMEM);
    cudaFuncSetAttribute(gemm_one<256, false, false, false>, cudaFuncAttributeMaxDynamicSharedMemorySize, GSMEM);

    cudaStream_t s1;
    cudaStreamCreateWithFlags(&s1, cudaStreamNonBlocking);
    cudaEvent_t evRoot, evX, evS0, evS1, evS2, evH1, evH2;
    cudaEventCreateWithFlags(&evRoot, cudaEventDisableTiming);
    cudaEventCreateWithFlags(&evX, cudaEventDisableTiming);
    cudaEventCreateWithFlags(&evS0, cudaEventDisableTiming);
    cudaEventCreateWithFlags(&evS1, cudaEventDisableTiming);
    cudaEventCreateWithFlags(&evS2, cudaEventDisableTiming);
    cudaEventCreateWithFlags(&evH1, cudaEventDisableTiming);
    cudaEventCreateWithFlags(&evH2, cudaEventDisableTiming);

    int agg_blocks1 = (NN * 32 + 255) / 256;
    int agg_blocks2 = (NN * 2 * 32 + 255) / 256;
    dim3 gg((NN + 127) / 128, 2);

    cudaEventRecord(evRoot, 0);
    cudaStreamWaitEvent(s1, evRoot, 0);

    // ---- side stream: conversions + self-GEMM layer 0 ----
    conv_x_kernel<<<(NN * 128 + 255) / 256, 256, 0, s1>>>(x);
    cudaEventRecord(evX, s1);
    conv_w_kernel<<<(2 * 256 * 128 + 255) / 256, 256, 0, s1>>>(Wl0, Wr0, Bh0, Bl0, 128);
    conv_w_kernel<<<(2 * 256 * 256 + 255) / 256, 256, 0, s1>>>(Wl1, Wr1, Bh1, Bl1, 256);
    conv_w_kernel<<<(2 * 256 * 256 + 255) / 256, 256, 0, s1>>>(Wl2, Wr2, Bh2, Bl2, 256);
    gemm_one<128, true, false, false><<<gg, 256, GSMEM, s1>>>(
        X, BhR0, BlR0, nullptr, nullptr, nullptr, nullptr, nullptr, nullptr, P, NN);
    cudaEventRecord(evS0, s1);

    // ---- main stream: CSR build ----
    zero_counts_kernel<<<(NN + 255) / 256, 256>>>();
    hist_kernel<<<(E + 255) / 256, 256>>>(dst, E);
    scan_kernel<<<1, 1024>>>();
    scatter_kernel<<<(E + 255) / 256, 256>>>(src, dst, E);

    // layer 0
    cudaStreamWaitEvent(0, evX, 0);
    agg_packed<1><<<agg_blocks1, 256>>>(X, Mn);
    cudaStreamWaitEvent(0, evS0, 0);
    gemm_one<128, false, true, true><<<gg, 256, GSMEM>>>(
        Mn, BhL0, BlL0, P, bl0, g0, b0, rm0, rv0, h1, NN);
    cudaEventRecord(evH1, 0);

    cudaStreamWaitEvent(s1, evH1, 0);
    gemm_one<256, true, false, false><<<gg, 256, GSMEM, s1>>>(
        h1, BhR1, BlR1, nullptr, nullptr, nullptr, nullptr, nullptr, nullptr, P, NN);
    cudaEventRecord(evS1, s1);

    // layer 1
    agg_packed<2><<<agg_blocks2, 256>>>(h1, Mn);
    cudaStreamWaitEvent(0, evS1, 0);
    gemm_one<256, false, true, true><<<gg, 256, GSMEM>>>(
        Mn, BhL1, BlL1, P, bl1, g1, b1, rm1, rv1, h2, NN);
    cudaEventRecord(evH2, 0);

    cudaStreamWaitEvent(s1, evH2, 0);
    gemm_one<256, true, false, false><<<gg, 256, GSMEM, s1>>>(
        h2, BhR2, BlR2, nullptr, nullptr, nullptr, nullptr, nullptr, nullptr, P, NN);
    cudaEventRecord(evS2, s1);

    // layer 2
    agg_packed<2><<<agg_blocks2, 256>>>(h2, Mn);
    cudaStreamWaitEvent(0, evS2, 0);
    gemm_one<256, false, false, false><<<gg, 256, GSMEM>>>(
        Mn, BhL2, BlL2, P, bl2, g2, b2, rm2, rv2, d_out, NN);

    cudaEventDestroy(evRoot);
    cudaEventDestroy(evX);
    cudaEventDestroy(evS0);
    cudaEventDestroy(evS1);
    cudaEventDestroy(evS2);
    cudaEventDestroy(evH1);
    cudaEventDestroy(evH2);
    cudaStreamDestroy(s1);
}

// round 8
// speedup vs baseline: 2.8867x; 1.0753x over previous
#include <cuda_runtime.h>
#include <cuda_bf16.h>
#include <cstdint>

#define NN 50000
#define EMAX 800000
#define EPS 1e-5f
#define HALF0 25088   // 196 * 128

// ======================= split bf16 pack/unpack =======================
__device__ __forceinline__ uint32_t pack_bf(float v) {
    __nv_bfloat16 h = __float2bfloat16(v);
    float hf = __bfloat162float(h);
    __nv_bfloat16 l = __float2bfloat16(v - hf);
    return ((uint32_t)__bfloat16_as_ushort(h) << 16) | (uint32_t)__bfloat16_as_ushort(l);
}
__device__ __forceinline__ float unpack_add(uint32_t u) {
    return __uint_as_float(u & 0xffff0000u) + __uint_as_float(u << 16);
}

__device__ __forceinline__ void cpasync16(uint32_t dst, const void* src) {
    asm volatile("cp.async.cg.shared.global [%0], [%1], 16;" :: "r"(dst), "l"(src));
}
__device__ __forceinline__ void cpcommit() { asm volatile("cp.async.commit_group;" ::: "memory"); }
__device__ __forceinline__ void cpwait0()  { asm volatile("cp.async.wait_group 0;" ::: "memory"); }

// ======================= scratch =======================
__device__ uint32_t g_X[NN * 128];
__device__ uint32_t g_h1[NN * 256];
__device__ uint32_t g_h2[NN * 256];
__device__ uint32_t g_M[NN * 256];
__device__ float    g_P[NN * 256];
__device__ __align__(16) __nv_bfloat16 g_Bh[2 * 256 * 128 + 2 * 2 * 256 * 256];
__device__ __align__(16) __nv_bfloat16 g_Bl[2 * 256 * 128 + 2 * 2 * 256 * 256];
__device__ int g_counts[NN];
__device__ int g_offsets[NN + 1];
__device__ int g_cursor[NN];
__device__ int g_esrc[EMAX];
__device__ int g_bsum[256];
__device__ int g_boff[256];

// ======================= CSR build =======================
__global__ void zero_counts_kernel() {
    int i = blockIdx.x * blockDim.x + threadIdx.x;
    if (i < NN) g_counts[i] = 0;
}
__global__ void hist_kernel(const int* __restrict__ dst, int E) {
    int e = blockIdx.x * blockDim.x + threadIdx.x;
    if (e < E) atomicAdd(&g_counts[dst[e]], 1);
}
// phase 1: per-block sums of 256 counts
__global__ void block_sums_kernel() {
    __shared__ int s[256];
    int i = blockIdx.x * 256 + threadIdx.x;
    s[threadIdx.x] = (i < NN) ? g_counts[i] : 0;
    __syncthreads();
    #pragma unroll
    for (int off = 128; off > 0; off >>= 1) {
        if (threadIdx.x < off) s[threadIdx.x] += s[threadIdx.x + off];
        __syncthreads();
    }
    if (threadIdx.x == 0) g_bsum[blockIdx.x] = s[0];
}
// phase 2: scan block sums (1 block, nb <= 256)
__global__ void scan_bsums_kernel(int nb) {
    __shared__ int s[256];
    int v = (threadIdx.x < nb) ? g_bsum[threadIdx.x] : 0;
    s[threadIdx.x] = v;
    __syncthreads();
    #pragma unroll
    for (int off = 1; off < 256; off <<= 1) {
        int t = (threadIdx.x >= off) ? s[threadIdx.x - off] : 0;
        __syncthreads();
        s[threadIdx.x] += t;
        __syncthreads();
    }
    if (threadIdx.x < nb) g_boff[threadIdx.x] = s[threadIdx.x] - v;
    if (threadIdx.x == 255) g_offsets[NN] = s[255];
}
// phase 3: per-block exclusive scan + base offset
__global__ void scan_final_kernel() {
    __shared__ int s[256];
    int i = blockIdx.x * 256 + threadIdx.x;
    int v = (i < NN) ? g_counts[i] : 0;
    s[threadIdx.x] = v;
    __syncthreads();
    #pragma unroll
    for (int off = 1; off < 256; off <<= 1) {
        int t = (threadIdx.x >= off) ? s[threadIdx.x - off] : 0;
        __syncthreads();
        s[threadIdx.x] += t;
        __syncthreads();
    }
    if (i < NN) {
        g_offsets[i] = g_boff[blockIdx.x] + s[threadIdx.x] - v;
        g_cursor[i] = 0;
    }
}
__global__ void scatter_kernel(const int* __restrict__ src, const int* __restrict__ dst, int E) {
    int e = blockIdx.x * blockDim.x + threadIdx.x;
    if (e < E) {
        int d = dst[e];
        int p = atomicAdd(&g_cursor[d], 1);
        g_esrc[g_offsets[d] + p] = src[e];
    }
}

// ======================= conversion =======================
__global__ void conv_x_kernel(const float* __restrict__ x) {
    int i = blockIdx.x * blockDim.x + threadIdx.x;
    if (i < NN * 128) g_X[i] = pack_bf(x[i]);
}
__global__ void conv_w_kernel(const float* __restrict__ Wl, const float* __restrict__ Wr,
                              __nv_bfloat16* __restrict__ Bh, __nv_bfloat16* __restrict__ Bl,
                              int K) {
    int i = blockIdx.x * blockDim.x + threadIdx.x;
    int tot = 2 * 256 * K;
    if (i >= tot) return;
    int mat = i / (256 * K);
    int r = i - mat * 256 * K;
    int n = r / K;
    int k = r - n * K;
    const float* W = mat ? Wr : Wl;
    float f = W[k * 256 + n];
    __nv_bfloat16 h = __float2bfloat16(f);
    __nv_bfloat16 l = __float2bfloat16(f - __bfloat162float(h));
    Bh[i] = h;
    Bl[i] = l;
}

// ======================= mean aggregation (node range) =======================
template <int NHALF>
__global__ __launch_bounds__(256) void agg_packed(const uint32_t* __restrict__ h,
                                                  uint32_t* __restrict__ mean,
                                                  int nodeBeg, int nodeEnd) {
    int gw = (blockIdx.x * blockDim.x + threadIdx.x) >> 5;
    int nNodes = nodeEnd - nodeBeg;
    if (gw >= nNodes * NHALF) return;
    int node, half;
    if (NHALF == 2) { node = nodeBeg + (gw >> 1); half = gw & 1; }
    else            { node = nodeBeg + gw;        half = 0; }
    int lane = threadIdx.x & 31;
    int beg = g_offsets[node], end = g_offsets[node + 1];

    const int RS = NHALF * 32;
    const uint4* base = reinterpret_cast<const uint4*>(h) + half * 32 + lane;

    float a0 = 0.f, a1 = 0.f, a2 = 0.f, a3 = 0.f;
    int e = beg;
    for (; e + 4 <= end; e += 4) {
        int s0 = g_esrc[e + 0];
        int s1 = g_esrc[e + 1];
        int s2 = g_esrc[e + 2];
        int s3 = g_esrc[e + 3];
        uint4 t0 = __ldg(base + (size_t)s0 * RS);
        uint4 t1 = __ldg(base + (size_t)s1 * RS);
        uint4 t2 = __ldg(base + (size_t)s2 * RS);
        uint4 t3 = __ldg(base + (size_t)s3 * RS);
        a0 += unpack_add(t0.x) + unpack_add(t1.x) + unpack_add(t2.x) + unpack_add(t3.x);
        a1 += unpack_add(t0.y) + unpack_add(t1.y) + unpack_add(t2.y) + unpack_add(t3.y);
        a2 += unpack_add(t0.z) + unpack_add(t1.z) + unpack_add(t2.z) + unpack_add(t3.z);
        a3 += unpack_add(t0.w) + unpack_add(t1.w) + unpack_add(t2.w) + unpack_add(t3.w);
    }
    for (; e < end; e++) {
        int s = g_esrc[e];
        uint4 t = __ldg(base + (size_t)s * RS);
        a0 += unpack_add(t.x);
        a1 += unpack_add(t.y);
        a2 += unpack_add(t.z);
        a3 += unpack_add(t.w);
    }

    int deg = end - beg;
    float inv = 1.0f / (float)(deg > 1 ? deg : 1);
    uint4 o;
    o.x = pack_bf(a0 * inv);
    o.y = pack_bf(a1 * inv);
    o.z = pack_bf(a2 * inv);
    o.w = pack_bf(a3 * inv);
    reinterpret_cast<uint4*>(mean)[(size_t)node * RS + half * 32 + lane] = o;
}

// ======================= mma.sync helper =======================
__device__ __forceinline__ void mma16816(float* c, const uint32_t* a, uint32_t b0, uint32_t b1) {
    asm("mma.sync.aligned.m16n8k16.row.col.f32.bf16.bf16.f32 "
        "{%0,%1,%2,%3}, {%4,%5,%6,%7}, {%8,%9}, {%0,%1,%2,%3};"
        : "+f"(c[0]), "+f"(c[1]), "+f"(c[2]), "+f"(c[3])
        : "r"(a[0]), "r"(a[1]), "r"(a[2]), "r"(a[3]), "r"(b0), "r"(b1));
}

// ======================= double-buffered single-matrix GEMM =======================
#define SST 40
#define PLANE_B (128 * SST * 2)
#define BUF_B   (4 * PLANE_B)
#define GSMEM   (2 * BUF_B)

template <int K, bool SELF, bool PACK_OUT, bool RELU>
__global__ __launch_bounds__(256, 2) void gemm_one(
    const uint32_t* __restrict__ A,
    const __nv_bfloat16* __restrict__ Bh, const __nv_bfloat16* __restrict__ Bl,
    const float* __restrict__ P,
    const float* __restrict__ blv, const float* __restrict__ gam,
    const float* __restrict__ bet, const float* __restrict__ rm,
    const float* __restrict__ rv,
    void* __restrict__ outv, int rowOff, int M)
{
    extern __shared__ __align__(16) char dsm[];
    constexpr int NC = K / 32;

    int tid = threadIdx.x;
    int lane = tid & 31;
    int wid = tid >> 5;
    int g = lane >> 2;
    int tig = lane & 3;
    int wm = wid & 3;
    int wn = wid >> 2;
    int mBase = rowOff + blockIdx.x * 128;
    int nBase = blockIdx.y * 128;

    float acc[2][8][4];
    #pragma unroll
    for (int mt = 0; mt < 2; mt++)
        #pragma unroll
        for (int nt = 0; nt < 8; nt++)
            #pragma unroll
            for (int q = 0; q < 4; q++) acc[mt][nt][q] = 0.f;

    auto stageB = [&](int kc, int buf) {
        char* base = dsm + buf * BUF_B;
        uint32_t dBh = (uint32_t)__cvta_generic_to_shared(base + 2 * PLANE_B);
        uint32_t dBl = (uint32_t)__cvta_generic_to_shared(base + 3 * PLANE_B);
        #pragma unroll
        for (int i = 0; i < 2; i++) {
            int lin = tid + i * 256;
            int row = lin >> 2;
            int c8 = lin & 3;
            uint32_t doff = (uint32_t)(row * (SST * 2) + c8 * 16);
            const __nv_bfloat16* sh = Bh + (size_t)(nBase + row) * K + kc * 32 + c8 * 8;
            const __nv_bfloat16* sl = Bl + (size_t)(nBase + row) * K + kc * 32 + c8 * 8;
            cpasync16(dBh + doff, sh);
            cpasync16(dBl + doff, sl);
        }
        cpcommit();
    };
    auto loadA = [&](int kc, uint2* pa) {
        #pragma unroll
        for (int i = 0; i < 8; i++) {
            int lin = tid + i * 256;
            int row = lin >> 4;
            int c2 = lin & 15;
            int grow = mBase + row;
            pa[i] = (grow < M) ? ((const uint2*)(A + (size_t)grow * K + kc * 32))[c2]
                               : make_uint2(0u, 0u);
        }
    };
    auto storeA = [&](int buf, const uint2* pa) {
        char* base = dsm + buf * BUF_B;
        __nv_bfloat16* sAh = (__nv_bfloat16*)(base);
        __nv_bfloat16* sAl = (__nv_bfloat16*)(base + PLANE_B);
        #pragma unroll
        for (int i = 0; i < 8; i++) {
            int lin = tid + i * 256;
            int row = lin >> 4;
            int c2 = lin & 15;
            uint32_t hu = (pa[i].x >> 16) | (pa[i].y & 0xffff0000u);
            uint32_t lu = (pa[i].x & 0xffffu) | (pa[i].y << 16);
            *(uint32_t*)&sAh[row * SST + c2 * 2] = hu;
            *(uint32_t*)&sAl[row * SST + c2 * 2] = lu;
        }
    };

    uint2 pa[8];
    stageB(0, 0);
    loadA(0, pa);
    storeA(0, pa);
    cpwait0();
    __syncthreads();

    for (int kc = 0; kc < NC; kc++) {
        int cur = kc & 1;
        int nxt = cur ^ 1;
        bool more = (kc + 1 < NC);
        if (more) {
            stageB(kc + 1, nxt);
            loadA(kc + 1, pa);
        }
        {
            char* base = dsm + cur * BUF_B;
            const __nv_bfloat16* sAh = (const __nv_bfloat16*)(base);
            const __nv_bfloat16* sAl = (const __nv_bfloat16*)(base + PLANE_B);
            const __nv_bfloat16* sBh = (const __nv_bfloat16*)(base + 2 * PLANE_B);
            const __nv_bfloat16* sBl = (const __nv_bfloat16*)(base + 3 * PLANE_B);
            #pragma unroll
            for (int ks = 0; ks < 2; ks++) {
                int k0 = ks * 16;
                uint32_t ah[2][4], al[2][4];
                #pragma unroll
                for (int mt = 0; mt < 2; mt++) {
                    int r0 = (wm * 32 + mt * 16 + g) * SST + k0 + 2 * tig;
                    ah[mt][0] = *(const uint32_t*)&sAh[r0];
                    ah[mt][1] = *(const uint32_t*)&sAh[r0 + 8 * SST];
                    ah[mt][2] = *(const uint32_t*)&sAh[r0 + 8];
                    ah[mt][3] = *(const uint32_t*)&sAh[r0 + 8 * SST + 8];
                    al[mt][0] = *(const uint32_t*)&sAl[r0];
                    al[mt][1] = *(const uint32_t*)&sAl[r0 + 8 * SST];
                    al[mt][2] = *(const uint32_t*)&sAl[r0 + 8];
                    al[mt][3] = *(const uint32_t*)&sAl[r0 + 8 * SST + 8];
                }
                #pragma unroll
                for (int nt = 0; nt < 8; nt++) {
                    int b0 = (wn * 64 + nt * 8 + g) * SST + k0 + 2 * tig;
                    uint32_t bh0 = *(const uint32_t*)&sBh[b0];
                    uint32_t bh1 = *(const uint32_t*)&sBh[b0 + 8];
                    uint32_t bl0 = *(const uint32_t*)&sBl[b0];
                    uint32_t bl1 = *(const uint32_t*)&sBl[b0 + 8];
                    #pragma unroll
                    for (int mt = 0; mt < 2; mt++) {
                        mma16816(acc[mt][nt], ah[mt], bh0, bh1);
                        mma16816(acc[mt][nt], al[mt], bh0, bh1);
                        mma16816(acc[mt][nt], ah[mt], bl0, bl1);
                    }
                }
            }
        }
        if (more) {
            storeA(nxt, pa);
            cpwait0();
        }
        __syncthreads();
    }

    if (SELF) {
        float* out = (float*)outv;
        #pragma unroll
        for (int nt = 0; nt < 8; nt++) {
            int c0 = nBase + wn * 64 + nt * 8 + 2 * tig;
            #pragma unroll
            for (int mt = 0; mt < 2; mt++) {
                int r0 = mBase + wm * 32 + mt * 16 + g;
                int r1 = r0 + 8;
                if (r0 < M)
                    *(float2*)(out + (size_t)r0 * 256 + c0) = make_float2(acc[mt][nt][0], acc[mt][nt][1]);
                if (r1 < M)
                    *(float2*)(out + (size_t)r1 * 256 + c0) = make_float2(acc[mt][nt][2], acc[mt][nt][3]);
            }
        }
    } else {
        uint32_t* out = (uint32_t*)outv;
        #pragma unroll
        for (int nt = 0; nt < 8; nt++) {
            int c0 = nBase + wn * 64 + nt * 8 + 2 * tig;
            int c1 = c0 + 1;
            float sc0 = gam[c0] * rsqrtf(rv[c0] + EPS);
            float sh0 = (blv[c0] - rm[c0]) * sc0 + bet[c0];
            float sc1 = gam[c1] * rsqrtf(rv[c1] + EPS);
            float sh1 = (blv[c1] - rm[c1]) * sc1 + bet[c1];
            #pragma unroll
            for (int mt = 0; mt < 2; mt++) {
                int r0 = mBase + wm * 32 + mt * 16 + g;
                int r1 = r0 + 8;
                if (r0 < M) {
                    float2 p = *(const float2*)(P + (size_t)r0 * 256 + c0);
                    float v00 = (acc[mt][nt][0] + p.x) * sc0 + sh0;
                    float v01 = (acc[mt][nt][1] + p.y) * sc1 + sh1;
                    if (RELU) { v00 = fmaxf(v00, 0.f); v01 = fmaxf(v01, 0.f); }
                    uint2 w;
                    w.x = PACK_OUT ? pack_bf(v00) : __float_as_uint(v00);
                    w.y = PACK_OUT ? pack_bf(v01) : __float_as_uint(v01);
                    *(uint2*)(out + (size_t)r0 * 256 + c0) = w;
                }
                if (r1 < M) {
                    float2 p = *(const float2*)(P + (size_t)r1 * 256 + c0);
                    float v10 = (acc[mt][nt][2] + p.x) * sc0 + sh0;
                    float v11 = (acc[mt][nt][3] + p.y) * sc1 + sh1;
                    if (RELU) { v10 = fmaxf(v10, 0.f); v11 = fmaxf(v11, 0.f); }
                    uint2 w;
                    w.x = PACK_OUT ? pack_bf(v10) : __float_as_uint(v10);
                    w.y = PACK_OUT ? pack_bf(v11) : __float_as_uint(v11);
                    *(uint2*)(out + (size_t)r1 * 256 + c0) = w;
                }
            }
        }
    }
}

// ======================= launch =======================
extern "C" void kernel_launch(void* const* d_in, const int* in_sizes, int n_in,
                              void* d_out, int out_size) {
    const float* x = (const float*)d_in[0];
    const int* ei = (const int*)d_in[1];
    int E = in_sizes[1] / 2;
    const int* src = ei;
    const int* dst = ei + E;

    const float* Wl0 = (const float*)d_in[2];
    const float* bl0 = (const float*)d_in[3];
    const float* Wr0 = (const float*)d_in[4];
    const float* g0 = (const float*)d_in[5];
    const float* b0 = (const float*)d_in[6];
    const float* rm0 = (const float*)d_in[7];
    const float* rv0 = (const float*)d_in[8];
    const float* Wl1 = (const float*)d_in[9];
    const float* bl1 = (const float*)d_in[10];
    const float* Wr1 = (const float*)d_in[11];
    const float* g1 = (const float*)d_in[12];
    const float* b1 = (const float*)d_in[13];
    const float* rm1 = (const float*)d_in[14];
    const float* rv1 = (const float*)d_in[15];
    const float* Wl2 = (const float*)d_in[16];
    const float* bl2 = (const float*)d_in[17];
    const float* Wr2 = (const float*)d_in[18];
    const float* g2 = (const float*)d_in[19];
    const float* b2 = (const float*)d_in[20];
    const float* rm2 = (const float*)d_in[21];
    const float* rv2 = (const float*)d_in[22];

    uint32_t *X, *h1, *h2, *Mn;
    float* P;
    __nv_bfloat16 *Bh, *Bl;
    cudaGetSymbolAddress((void**)&X, g_X);
    cudaGetSymbolAddress((void**)&h1, g_h1);
    cudaGetSymbolAddress((void**)&h2, g_h2);
    cudaGetSymbolAddress((void**)&Mn, g_M);
    cudaGetSymbolAddress((void**)&P, g_P);
    cudaGetSymbolAddress((void**)&Bh, g_Bh);
    cudaGetSymbolAddress((void**)&Bl, g_Bl);
    __nv_bfloat16* Bh0 = Bh;
    __nv_bfloat16* Bh1 = Bh + 2 * 256 * 128;
    __nv_bfloat16* Bh2 = Bh1 + 2 * 256 * 256;
    __nv_bfloat16* Bl0 = Bl;
    __nv_bfloat16* Bl1 = Bl + 2 * 256 * 128;
    __nv_bfloat16* Bl2 = Bl1 + 2 * 256 * 256;
    __nv_bfloat16 *BhL0 = Bh0, *BhR0 = Bh0 + 256 * 128;
    __nv_bfloat16 *BlL0 = Bl0, *BlR0 = Bl0 + 256 * 128;
    __nv_bfloat16 *BhL1 = Bh1, *BhR1 = Bh1 + 256 * 256;
    __nv_bfloat16 *BlL1 = Bl1, *BlR1 = Bl1 + 256 * 256;
    __nv_bfloat16 *BhL2 = Bh2, *BhR2 = Bh2 + 256 * 256;
    __nv_bfloat16 *BlL2 = Bl2, *BlR2 = Bl2 + 256 * 256;

    cudaFuncSetAttribute(gemm_one<128, true, false, false>, cudaFuncAttributeMaxDynamicSharedMemorySize, GSMEM);
    cudaFuncSetAttribute(gemm_one<256, true, false, false>, cudaFuncAttributeMaxDynamicSharedMemorySize, GSMEM);
    cudaFuncSetAttribute(gemm_one<128, false, true, true>, cudaFuncAttributeMaxDynamicSharedMemorySize, GSMEM);
    cudaFuncSetAttribute(gemm_one<256, false, true, true>, cudaFuncAttributeMaxDynamicSharedMemorySize, GSMEM);
    cudaFuncSetAttribute(gemm_one<256, false, false, false>, cudaFuncAttributeMaxDynamicSharedMemorySize, GSMEM);

    cudaStream_t s1, s2;
    cudaStreamCreateWithFlags(&s1, cudaStreamNonBlocking);
    cudaStreamCreateWithFlags(&s2, cudaStreamNonBlocking);

    cudaEvent_t evRoot, evX, evP[3], evA0[3], evG0[3], evH[2];
    cudaEventCreateWithFlags(&evRoot, cudaEventDisableTiming);
    cudaEventCreateWithFlags(&evX, cudaEventDisableTiming);
    for (int i = 0; i < 3; i++) {
        cudaEventCreateWithFlags(&evP[i], cudaEventDisableTiming);
        cudaEventCreateWithFlags(&evA0[i], cudaEventDisableTiming);
        cudaEventCreateWithFlags(&evG0[i], cudaEventDisableTiming);
    }
    for (int i = 0; i < 2; i++) cudaEventCreateWithFlags(&evH[i], cudaEventDisableTiming);

    // grids
    const int nScanBlocks = (NN + 255) / 256;                       // 196
    dim3 ggH0(HALF0 / 128, 2);                                      // 196 blocks
    dim3 ggH1((NN - HALF0 + 127) / 128, 2);                         // 195 blocks
    dim3 ggFull((NN + 127) / 128, 2);
    auto aggBlocks = [](int nodes, int nhalf) { return (nodes * nhalf * 32 + 255) / 256; };

    cudaEventRecord(evRoot, 0);
    cudaStreamWaitEvent(s1, evRoot, 0);
    cudaStreamWaitEvent(s2, evRoot, 0);

    // ---- s1: conversions + self-GEMM layer 0 (full range) ----
    conv_x_kernel<<<(NN * 128 + 255) / 256, 256, 0, s1>>>(x);
    cudaEventRecord(evX, s1);
    conv_w_kernel<<<(2 * 256 * 128 + 255) / 256, 256, 0, s1>>>(Wl0, Wr0, Bh0, Bl0, 128);
    conv_w_kernel<<<(2 * 256 * 256 + 255) / 256, 256, 0, s1>>>(Wl1, Wr1, Bh1, Bl1, 256);
    conv_w_kernel<<<(2 * 256 * 256 + 255) / 256, 256, 0, s1>>>(Wl2, Wr2, Bh2, Bl2, 256);
    gemm_one<128, true, false, false><<<ggFull, 256, GSMEM, s1>>>(
        X, BhR0, BlR0, nullptr, nullptr, nullptr, nullptr, nullptr, nullptr, P, 0, NN);
    cudaEventRecord(evP[0], s1);

    // ---- main: CSR build (parallel scan) ----
    zero_counts_kernel<<<(NN + 255) / 256, 256>>>();
    hist_kernel<<<(E + 255) / 256, 256>>>(dst, E);
    block_sums_kernel<<<nScanBlocks, 256>>>();
    scan_bsums_kernel<<<1, 256>>>(nScanBlocks);
    scan_final_kernel<<<nScanBlocks, 256>>>();
    scatter_kernel<<<(E + 255) / 256, 256>>>(src, dst, E);

    // =========== layer 0 ===========
    cudaStreamWaitEvent(0, evX, 0);
    agg_packed<1><<<aggBlocks(HALF0, 1), 256>>>(X, Mn, 0, HALF0);
    cudaEventRecord(evA0[0], 0);
    agg_packed<1><<<aggBlocks(NN - HALF0, 1), 256>>>(X, Mn, HALF0, NN);

    cudaStreamWaitEvent(s2, evA0[0], 0);
    cudaStreamWaitEvent(s2, evP[0], 0);
    gemm_one<128, false, true, true><<<ggH0, 256, GSMEM, s2>>>(
        Mn, BhL0, BlL0, P, bl0, g0, b0, rm0, rv0, h1, 0, NN);
    cudaEventRecord(evG0[0], s2);

    cudaStreamWaitEvent(0, evP[0], 0);
    gemm_one<128, false, true, true><<<ggH1, 256, GSMEM>>>(
        Mn, BhL0, BlL0, P, bl0, g0, b0, rm0, rv0, h1, HALF0, NN);
    cudaStreamWaitEvent(0, evG0[0], 0);
    cudaEventRecord(evH[0], 0);   // h1 fully written

    // s1: self-GEMM layer 1
    cudaStreamWaitEvent(s1, evH[0], 0);
    gemm_one<256, true, false, false><<<ggFull, 256, GSMEM, s1>>>(
        h1, BhR1, BlR1, nullptr, nullptr, nullptr, nullptr, nullptr, nullptr, P, 0, NN);
    cudaEventRecord(evP[1], s1);

    // =========== layer 1 ===========
    agg_packed<2><<<aggBlocks(HALF0, 2), 256>>>(h1, Mn, 0, HALF0);
    cudaEventRecord(evA0[1], 0);
    agg_packed<2><<<aggBlocks(NN - HALF0, 2), 256>>>(h1, Mn, HALF0, NN);

    cudaStreamWaitEvent(s2, evA0[1], 0);
    cudaStreamWaitEvent(s2, evP[1], 0);
    gemm_one<256, false, true, true><<<ggH0, 256, GSMEM, s2>>>(
        Mn, BhL1, BlL1, P, bl1, g1, b1, rm1, rv1, h2, 0, NN);
    cudaEventRecord(evG0[1], s2);

    cudaStreamWaitEvent(0, evP[1], 0);
    gemm_one<256, false, true, true><<<ggH1, 256, GSMEM>>>(
        Mn, BhL1, BlL1, P, bl1, g1, b1, rm1, rv1, h2, HALF0, NN);
    cudaStreamWaitEvent(0, evG0[1], 0);
    cudaEventRecord(evH[1], 0);   // h2 fully written

    // s1: self-GEMM layer 2
    cudaStreamWaitEvent(s1, evH[1], 0);
    gemm_one<256, true, false, false><<<ggFull, 256, GSMEM, s1>>>(
        h2, BhR2, BlR2, nullptr, nullptr, nullptr, nullptr, nullptr, nullptr, P, 0, NN);
    cudaEventRecord(evP[2], s1);

    // =========== layer 2 ===========
    agg_packed<2><<<aggBlocks(HALF0, 2), 256>>>(h2, Mn, 0, HALF0);
    cudaEventRecord(evA0[2], 0);
    agg_packed<2><<<aggBlocks(NN - HALF0, 2), 256>>>(h2, Mn, HALF0, NN);

    cudaStreamWaitEvent(s2, evA0[2], 0);
    cudaStreamWaitEvent(s2, evP[2], 0);
    gemm_one<256, false, false, false><<<ggH0, 256, GSMEM, s2>>>(
        Mn, BhL2, BlL2, P, bl2, g2, b2, rm2, rv2, d_out, 0, NN);
    cudaEventRecord(evG0[2], s2);

    cudaStreamWaitEvent(0, evP[2], 0);
    gemm_one<256, false, false, false><<<ggH1, 256, GSMEM>>>(
        Mn, BhL2, BlL2, P, bl2, g2, b2, rm2, rv2, d_out, HALF0, NN);
    cudaStreamWaitEvent(0, evG0[2], 0);   // join s2 tail into main before capture end

    cudaEventDestroy(evRoot);
    cudaEventDestroy(evX);
    for (int i = 0; i < 3; i++) {
        cudaEventDestroy(evP[i]);
        cudaEventDestroy(evA0[i]);
        cudaEventDestroy(evG0[i]);
    }
    for (int i = 0; i < 2; i++) cudaEventDestroy(evH[i]);
    cudaStreamDestroy(s1);
    cudaStreamDestroy(s2);
}